// round 5
// baseline (speedup 1.0000x reference)
#include <cuda_runtime.h>
#include <math.h>

// Problem constants
#define BB 4
#define TT 2048
#define CC 1024
#define HH 16
#define HS 64
#define MM (BB*TT)   // 8192

// Scratch (device globals: no allocations allowed)
__device__ float g_q[(size_t)BB*HH*TT*HS];   // [B,H,T,HS]
__device__ float g_k[(size_t)BB*HH*TT*HS];
__device__ float g_v[(size_t)BB*HH*TT*HS];
__device__ float g_y[(size_t)BB*TT*CC];      // [B,T,H*HS]

// ---------------------------------------------------------------------------
// Kernel 1: fused QKV projection.
// q[b,h,t,d] = sum_c x[b,t,c] * Wq[h,c,d]   (same for k,v via blockIdx.z)
// Block tile: 128 rows (m = b*T+t) x 64 cols (d, one full head).
// 256 threads, each computes 8x4 outputs. K-tile = 16.
// ---------------------------------------------------------------------------
__global__ __launch_bounds__(256) void qkv_kernel(
    const float* __restrict__ x,
    const float* __restrict__ Wq,
    const float* __restrict__ Wk,
    const float* __restrict__ Wv)
{
    const int m0    = blockIdx.x * 128;
    const int h     = blockIdx.y;
    const int which = blockIdx.z;
    const float* W  = (which == 0) ? Wq : (which == 1) ? Wk : Wv;
    float* outp     = (which == 0) ? g_q : (which == 1) ? g_k : g_v;

    __shared__ float Xs[16][129];   // [c][m], transposed for broadcast reads
    __shared__ float Ws[16][65];    // [c][d]

    const int t  = threadIdx.x;
    const int tx = t & 15;          // col group (4 cols)
    const int ty = t >> 4;          // row group (8 rows)

    float acc[8][4];
#pragma unroll
    for (int i = 0; i < 8; i++)
#pragma unroll
        for (int j = 0; j < 4; j++) acc[i][j] = 0.f;

    const float* Wh = W + (size_t)h * CC * HS;

    for (int c0 = 0; c0 < CC; c0 += 16) {
#pragma unroll
        for (int i = 0; i < 8; i++) {           // 128*16 / 256
            int idx = t + i * 256;
            int m = idx >> 4, c = idx & 15;
            Xs[c][m] = x[(size_t)(m0 + m) * CC + c0 + c];
        }
#pragma unroll
        for (int i = 0; i < 4; i++) {           // 16*64 / 256
            int idx = t + i * 256;
            int c = idx >> 6, d = idx & 63;
            Ws[c][d] = Wh[(size_t)(c0 + c) * HS + d];
        }
        __syncthreads();
#pragma unroll
        for (int kk = 0; kk < 16; kk++) {
            float a[8], b[4];
#pragma unroll
            for (int i = 0; i < 8; i++) a[i] = Xs[kk][ty * 8 + i];
#pragma unroll
            for (int j = 0; j < 4; j++) b[j] = Ws[kk][tx * 4 + j];
#pragma unroll
            for (int i = 0; i < 8; i++)
#pragma unroll
                for (int j = 0; j < 4; j++) acc[i][j] += a[i] * b[j];
        }
        __syncthreads();
    }

#pragma unroll
    for (int i = 0; i < 8; i++) {
        int m  = m0 + ty * 8 + i;
        int b  = m / TT;
        int tt = m - b * TT;
        float* o = outp + ((((size_t)b * HH + h) * TT + tt) * HS) + tx * 4;
#pragma unroll
        for (int j = 0; j < 4; j++) o[j] = acc[i][j];
    }
}

// ---------------------------------------------------------------------------
// Kernel 2: causal flash attention, fp32, HS=64.
// One block per (q-tile of 64 rows, b*h). 256 threads, 4x4 microtiles.
// Online softmax with warp-shuffle row reductions (rows live on 16 lanes).
// ---------------------------------------------------------------------------
__global__ __launch_bounds__(256) void attn_kernel()
{
    const int qt = blockIdx.x;           // 0..T/64-1
    const int bh = blockIdx.y;           // 0..B*H-1
    const int q0 = qt * 64;

    const float* Q = g_q + (size_t)bh * TT * HS;
    const float* K = g_k + (size_t)bh * TT * HS;
    const float* V = g_v + (size_t)bh * TT * HS;

    extern __shared__ float sm[];
    float* Qs = sm;                 // 64*65
    float* Ks = Qs + 64 * 65;
    float* Vs = Ks + 64 * 65;
    float* Ps = Vs + 64 * 65;

    const int t  = threadIdx.x;
    const int tx = t & 15;          // 4 cols
    const int ty = t >> 4;          // 4 rows

#pragma unroll
    for (int i = 0; i < 16; i++) {  // 64*64 / 256
        int idx = t + i * 256;
        int r = idx >> 6, d = idx & 63;
        Qs[r * 65 + d] = Q[(size_t)(q0 + r) * HS + d];
    }

    float m_run[4], l_run[4], O[4][4];
#pragma unroll
    for (int i = 0; i < 4; i++) {
        m_run[i] = -INFINITY;
        l_run[i] = 0.f;
#pragma unroll
        for (int j = 0; j < 4; j++) O[i][j] = 0.f;
    }

    const float scale = 0.125f;     // 1/sqrt(64)

    for (int jt = 0; jt <= qt; jt++) {
        const int k0 = jt * 64;
        __syncthreads();            // previous P*V done before overwriting K/V
#pragma unroll
        for (int i = 0; i < 16; i++) {
            int idx = t + i * 256;
            int r = idx >> 6, d = idx & 63;
            Ks[r * 65 + d] = K[(size_t)(k0 + r) * HS + d];
            Vs[r * 65 + d] = V[(size_t)(k0 + r) * HS + d];
        }
        __syncthreads();

        // S = Q * K^T (4x4 per thread)
        float S[4][4];
#pragma unroll
        for (int i = 0; i < 4; i++)
#pragma unroll
            for (int j = 0; j < 4; j++) S[i][j] = 0.f;

        for (int d = 0; d < 64; d++) {
            float a[4], b[4];
#pragma unroll
            for (int i = 0; i < 4; i++) a[i] = Qs[(ty * 4 + i) * 65 + d];
#pragma unroll
            for (int j = 0; j < 4; j++) b[j] = Ks[(tx * 4 + j) * 65 + d];
#pragma unroll
            for (int i = 0; i < 4; i++)
#pragma unroll
                for (int j = 0; j < 4; j++) S[i][j] += a[i] * b[j];
        }

        const bool diag = (jt == qt);
#pragma unroll
        for (int i = 0; i < 4; i++) {
#pragma unroll
            for (int j = 0; j < 4; j++) {
                S[i][j] *= scale;
                if (diag && (k0 + tx * 4 + j > q0 + ty * 4 + i))
                    S[i][j] = -INFINITY;
            }
        }

        // Online softmax update. Row r = ty*4+i lives on 16 lanes (same ty).
#pragma unroll
        for (int i = 0; i < 4; i++) {
            float mx = S[i][0];
#pragma unroll
            for (int j = 1; j < 4; j++) mx = fmaxf(mx, S[i][j]);
#pragma unroll
            for (int off = 8; off >= 1; off >>= 1)
                mx = fmaxf(mx, __shfl_xor_sync(0xffffffffu, mx, off));
            float mnew  = fmaxf(m_run[i], mx);
            float alpha = __expf(m_run[i] - mnew);   // 0 on first tile
            m_run[i] = mnew;
            float ls = 0.f;
#pragma unroll
            for (int j = 0; j < 4; j++) {
                S[i][j] = __expf(S[i][j] - mnew);    // -inf -> 0
                ls += S[i][j];
            }
#pragma unroll
            for (int off = 8; off >= 1; off >>= 1)
                ls += __shfl_xor_sync(0xffffffffu, ls, off);
            l_run[i] = l_run[i] * alpha + ls;
#pragma unroll
            for (int j = 0; j < 4; j++) O[i][j] *= alpha;
        }

        // Stage P, then O += P * V
#pragma unroll
        for (int i = 0; i < 4; i++)
#pragma unroll
            for (int j = 0; j < 4; j++)
                Ps[(ty * 4 + i) * 65 + tx * 4 + j] = S[i][j];
        __syncthreads();

        for (int s = 0; s < 64; s++) {
            float a[4], b[4];
#pragma unroll
            for (int i = 0; i < 4; i++) a[i] = Ps[(ty * 4 + i) * 65 + s];
#pragma unroll
            for (int j = 0; j < 4; j++) b[j] = Vs[s * 65 + tx * 4 + j];
#pragma unroll
            for (int i = 0; i < 4; i++)
#pragma unroll
                for (int j = 0; j < 4; j++) O[i][j] += a[i] * b[j];
        }
    }

    // Write y in [B,T,H*HS] layout
    const int b = bh >> 4;
    const int h = bh & 15;
#pragma unroll
    for (int i = 0; i < 4; i++) {
        const float inv = 1.f / l_run[i];
        const int tt = q0 + ty * 4 + i;
        float* o = g_y + (((size_t)b * TT + tt) * HH + h) * HS + tx * 4;
#pragma unroll
        for (int j = 0; j < 4; j++) o[j] = O[i][j] * inv;
    }
}

// ---------------------------------------------------------------------------
// Kernel 3: output projection. out[m,n] = bo[n] + sum_k y[m,k] * Wo[n,k]
// Block tile 128x64, 256 threads, 8x4 per thread, K-tile = 16.
// ---------------------------------------------------------------------------
__global__ __launch_bounds__(256) void outproj_kernel(
    const float* __restrict__ Wo,
    const float* __restrict__ bo,
    float* __restrict__ out)
{
    const int m0 = blockIdx.x * 128;
    const int n0 = blockIdx.y * 64;

    __shared__ float Ys[16][129];   // [k][m]
    __shared__ float Ws[16][65];    // [k][n]

    const int t  = threadIdx.x;
    const int tx = t & 15;
    const int ty = t >> 4;

    float acc[8][4];
#pragma unroll
    for (int i = 0; i < 8; i++)
#pragma unroll
        for (int j = 0; j < 4; j++) acc[i][j] = 0.f;

    for (int k0 = 0; k0 < CC; k0 += 16) {
#pragma unroll
        for (int i = 0; i < 8; i++) {
            int idx = t + i * 256;
            int m = idx >> 4, c = idx & 15;
            Ys[c][m] = g_y[(size_t)(m0 + m) * CC + k0 + c];
        }
#pragma unroll
        for (int i = 0; i < 4; i++) {
            int idx = t + i * 256;
            int kk = idx & 15, n = idx >> 4;
            Ws[kk][n] = Wo[(size_t)(n0 + n) * CC + k0 + kk];
        }
        __syncthreads();
#pragma unroll
        for (int kk = 0; kk < 16; kk++) {
            float a[8], b[4];
#pragma unroll
            for (int i = 0; i < 8; i++) a[i] = Ys[kk][ty * 8 + i];
#pragma unroll
            for (int j = 0; j < 4; j++) b[j] = Ws[kk][tx * 4 + j];
#pragma unroll
            for (int i = 0; i < 8; i++)
#pragma unroll
                for (int j = 0; j < 4; j++) acc[i][j] += a[i] * b[j];
        }
        __syncthreads();
    }

#pragma unroll
    for (int i = 0; i < 8; i++) {
        int m = m0 + ty * 8 + i;
        float* o = out + (size_t)m * CC + n0 + tx * 4;
#pragma unroll
        for (int j = 0; j < 4; j++) o[j] = acc[i][j] + bo[n0 + tx * 4 + j];
    }
}

// ---------------------------------------------------------------------------
extern "C" void kernel_launch(void* const* d_in, const int* in_sizes, int n_in,
                              void* d_out, int out_size)
{
    const float* x  = (const float*)d_in[0];
    const float* Wq = (const float*)d_in[1];
    const float* Wk = (const float*)d_in[2];
    const float* Wv = (const float*)d_in[3];
    const float* Wo = (const float*)d_in[4];
    const float* bo = (const float*)d_in[5];
    float* out = (float*)d_out;

    qkv_kernel<<<dim3(MM / 128, HH, 3), 256>>>(x, Wq, Wk, Wv);

    const size_t smem = 4 * 64 * 65 * sizeof(float);   // ~66.6 KB
    cudaFuncSetAttribute(attn_kernel,
                         cudaFuncAttributeMaxDynamicSharedMemorySize,
                         (int)smem);
    attn_kernel<<<dim3(TT / 64, BB * HH), 256, smem>>>();

    outproj_kernel<<<dim3(MM / 128, CC / 64), 256>>>(Wo, bo, out);
}

// round 7
// speedup vs baseline: 1.5485x; 1.5485x over previous
#include <cuda_runtime.h>
#include <cuda_bf16.h>
#include <math.h>
#include <cstdint>

// Problem constants
#define BB 4
#define TT 2048
#define CC 1024
#define HH 16
#define HS 64
#define MM (BB*TT)   // 8192

// Scratch (device globals: no allocations allowed)
__device__ float g_q[(size_t)BB*HH*TT*HS];   // [B,H,T,HS]
__device__ float g_k[(size_t)BB*HH*TT*HS];
__device__ float g_v[(size_t)BB*HH*TT*HS];
__device__ float g_y[(size_t)BB*TT*CC];      // [B,T,H*HS]

// Split-bf16 scratch (hi + lo so hi+lo ~= fp32 to ~16 mantissa bits)
__device__ __nv_bfloat16 g_xhi[(size_t)MM*CC],  g_xlo[(size_t)MM*CC];
__device__ __nv_bfloat16 g_wt_hi[(size_t)3*HH*HS*CC], g_wt_lo[(size_t)3*HH*HS*CC]; // W^T: [which][h*HS+d][c]
__device__ __nv_bfloat16 g_wo_hi[(size_t)CC*CC], g_wo_lo[(size_t)CC*CC];           // [n][k]
__device__ __nv_bfloat16 g_yhi[(size_t)MM*CC],  g_ylo[(size_t)MM*CC];

// ---------------------------------------------------------------------------
// Warp-MMA helpers (compute_103-safe: sm_80+ mma.sync / ldmatrix only)
// ---------------------------------------------------------------------------
__device__ __forceinline__ uint32_t smem_u32(const void* p) {
    uint32_t a;
    asm("{ .reg .u64 t; cvta.to.shared.u64 t, %1; cvt.u32.u64 %0, t; }"
        : "=r"(a) : "l"(p));
    return a;
}

#define LDSM4(r, addr) \
    asm volatile("ldmatrix.sync.aligned.m8n8.x4.shared.b16 {%0,%1,%2,%3}, [%4];" \
        : "=r"((r)[0]), "=r"((r)[1]), "=r"((r)[2]), "=r"((r)[3]) : "r"(addr))

#define MMA_BF16(c, a, b) \
    asm volatile("mma.sync.aligned.m16n8k16.row.col.f32.bf16.bf16.f32 " \
        "{%0,%1,%2,%3}, {%4,%5,%6,%7}, {%8,%9}, {%0,%1,%2,%3};" \
        : "+f"((c)[0]), "+f"((c)[1]), "+f"((c)[2]), "+f"((c)[3]) \
        : "r"((a)[0]), "r"((a)[1]), "r"((a)[2]), "r"((a)[3]), \
          "r"((b)[0]), "r"((b)[1]))

__device__ __forceinline__ void split1(float v, __nv_bfloat16& h, __nv_bfloat16& l) {
    h = __float2bfloat16(v);
    l = __float2bfloat16(v - __bfloat162float(h));
}

// ---------------------------------------------------------------------------
// Prep kernels: fp32 -> (hi, lo) bf16
// ---------------------------------------------------------------------------
__global__ __launch_bounds__(256) void cvt_split(const float* __restrict__ s,
                                                 __nv_bfloat16* __restrict__ hi,
                                                 __nv_bfloat16* __restrict__ lo)
{
    size_t i4 = (size_t)blockIdx.x * 256 + threadIdx.x;
    float4 v = reinterpret_cast<const float4*>(s)[i4];
    __nv_bfloat16 h[4], l[4];
    split1(v.x, h[0], l[0]); split1(v.y, h[1], l[1]);
    split1(v.z, h[2], l[2]); split1(v.w, h[3], l[3]);
    reinterpret_cast<uint2*>(hi)[i4] =
        make_uint2((uint32_t)__bfloat16_as_ushort(h[0]) | ((uint32_t)__bfloat16_as_ushort(h[1]) << 16),
                   (uint32_t)__bfloat16_as_ushort(h[2]) | ((uint32_t)__bfloat16_as_ushort(h[3]) << 16));
    reinterpret_cast<uint2*>(lo)[i4] =
        make_uint2((uint32_t)__bfloat16_as_ushort(l[0]) | ((uint32_t)__bfloat16_as_ushort(l[1]) << 16),
                   (uint32_t)__bfloat16_as_ushort(l[2]) | ((uint32_t)__bfloat16_as_ushort(l[3]) << 16));
}

// Transpose-convert W[h,c,d] -> wt[which][h*HS+d][c] with smem tile transpose.
__global__ void cvt_w_t(const float* __restrict__ Wq,
                        const float* __restrict__ Wk,
                        const float* __restrict__ Wv)
{
    __shared__ float ts[32][33];
    const int which = blockIdx.z / HH;
    const int h     = blockIdx.z % HH;
    const float* W  = (which == 0) ? Wq : (which == 1) ? Wk : Wv;
    const int c0 = blockIdx.x * 32;
    const int d0 = blockIdx.y * 32;

    for (int i = threadIdx.y; i < 32; i += 8)
        ts[i][threadIdx.x] = W[((size_t)h * CC + c0 + i) * HS + d0 + threadIdx.x];
    __syncthreads();

    __nv_bfloat16* hi = g_wt_hi + (size_t)which * HH * HS * CC;
    __nv_bfloat16* lo = g_wt_lo + (size_t)which * HH * HS * CC;
    for (int i = threadIdx.y; i < 32; i += 8) {
        int d = d0 + i, c = c0 + threadIdx.x;
        float v = ts[threadIdx.x][i];
        __nv_bfloat16 vh, vl;
        split1(v, vh, vl);
        size_t o = (size_t)(h * HS + d) * CC + c;
        hi[o] = vh;
        lo[o] = vl;
    }
}

// ---------------------------------------------------------------------------
// Split-bf16 HMMA GEMM: D[128,128] += A[128,1024] * B[128,1024]^T
// (Ahi*Bhi + Alo*Bhi + Ahi*Blo, fp32 accum).
// mode 0: QKV  (A = x split; B = wt[z]; out -> g_{q,k,v} in [B,H,T,HS])
// mode 1: out-proj (A = y split; B = Wo split; out -> d_out + bias)
// 256 threads = 8 warps (2 x 4), warp tile 64 x 32, BK = 64.
// SMEM: 4 buffers of [128 rows][128 bytes], XOR-swizzled, 64 KB total.
// ---------------------------------------------------------------------------
__global__ __launch_bounds__(256) void hmma_gemm(const float* __restrict__ bias,
                                                 float* __restrict__ out_direct,
                                                 int mode)
{
    extern __shared__ unsigned char smem[];
    const uint32_t sb = smem_u32(smem);
    const int tid = threadIdx.x;
    const int wid = tid >> 5, lid = tid & 31;
    const int m0  = blockIdx.x * 128;
    const int warp_m = (wid & 1) * 64;
    const int warp_n = (wid >> 1) * 32;
    const int nbase  = blockIdx.y * 128;

    const __nv_bfloat16 *Ahi, *Alo, *Bhi, *Blo;
    float* outp = nullptr;
    if (mode == 0) {
        const int z = blockIdx.z;
        Ahi = g_xhi; Alo = g_xlo;
        const size_t wo = (size_t)z * HH * HS * CC + (size_t)nbase * CC;
        Bhi = g_wt_hi + wo; Blo = g_wt_lo + wo;
        outp = (z == 0) ? g_q : (z == 1) ? g_k : g_v;
    } else {
        Ahi = g_yhi; Alo = g_ylo;
        Bhi = g_wo_hi + (size_t)nbase * CC;
        Blo = g_wo_lo + (size_t)nbase * CC;
    }

    float acc[4][4][4];
#pragma unroll
    for (int i = 0; i < 4; i++)
#pragma unroll
        for (int j = 0; j < 4; j++)
#pragma unroll
            for (int r = 0; r < 4; r++) acc[i][j][r] = 0.f;

    for (int c0 = 0; c0 < CC; c0 += 64) {
        __syncthreads();
        // Stage 4 tiles: [128][64] bf16 each = 128B rows, XOR-swizzled.
#pragma unroll
        for (int it = 0; it < 4; it++) {
            int idx = tid + it * 256;               // 1024 uint4 per buffer
            int m = idx >> 3, kv = idx & 7;
            uint32_t soff = (uint32_t)(m * 128 + ((kv ^ (m & 7)) << 4));
            size_t ga = (size_t)(m0 + m) * CC + c0 + kv * 8;
            size_t gb = (size_t)m * CC + c0 + kv * 8;
            *reinterpret_cast<uint4*>(smem + soff)         = *reinterpret_cast<const uint4*>(Ahi + ga);
            *reinterpret_cast<uint4*>(smem + 16384 + soff) = *reinterpret_cast<const uint4*>(Alo + ga);
            *reinterpret_cast<uint4*>(smem + 32768 + soff) = *reinterpret_cast<const uint4*>(Bhi + gb);
            *reinterpret_cast<uint4*>(smem + 49152 + soff) = *reinterpret_cast<const uint4*>(Blo + gb);
        }
        __syncthreads();

#pragma unroll
        for (int ks = 0; ks < 4; ks++) {
            uint32_t aHi[4][4], aLo[4][4], bHi[4][2], bLo[4][2];
            const int kb = ks * 2 + (lid >> 4);     // 16B block within row
#pragma unroll
            for (int i = 0; i < 4; i++) {
                int row = warp_m + i * 16 + (lid & 15);
                uint32_t ad = sb + (uint32_t)(row * 128 + ((kb ^ (row & 7)) << 4));
                LDSM4(aHi[i], ad);
                LDSM4(aLo[i], ad + 16384);
            }
#pragma unroll
            for (int nb = 0; nb < 2; nb++) {
                int row = warp_n + nb * 16 + (lid & 15);
                uint32_t ad = sb + 32768 + (uint32_t)(row * 128 + ((kb ^ (row & 7)) << 4));
                uint32_t q[4];
                LDSM4(q, ad);
                bHi[nb*2][0] = q[0]; bHi[nb*2][1] = q[2];
                bHi[nb*2+1][0] = q[1]; bHi[nb*2+1][1] = q[3];
                LDSM4(q, ad + 16384);
                bLo[nb*2][0] = q[0]; bLo[nb*2][1] = q[2];
                bLo[nb*2+1][0] = q[1]; bLo[nb*2+1][1] = q[3];
            }
#pragma unroll
            for (int i = 0; i < 4; i++)
#pragma unroll
                for (int j = 0; j < 4; j++) {
                    MMA_BF16(acc[i][j], aHi[i], bHi[j]);
                    MMA_BF16(acc[i][j], aLo[i], bHi[j]);
                    MMA_BF16(acc[i][j], aHi[i], bLo[j]);
                }
        }
    }

    // Epilogue: direct stores from C fragments
    const int g = lid >> 2, t4 = lid & 3;
#pragma unroll
    for (int i = 0; i < 4; i++) {
#pragma unroll
        for (int j = 0; j < 4; j++) {
            const int n = nbase + warp_n + j * 8 + t4 * 2;
            const int r0 = m0 + warp_m + i * 16 + g;
            const int r1 = r0 + 8;
            if (mode == 0) {
                const int head = n >> 6, d = n & 63;
                {
                    int b = r0 >> 11, tt = r0 & (TT - 1);
                    float2* o = reinterpret_cast<float2*>(
                        outp + (((size_t)b * HH + head) * TT + tt) * HS + d);
                    *o = make_float2(acc[i][j][0], acc[i][j][1]);
                }
                {
                    int b = r1 >> 11, tt = r1 & (TT - 1);
                    float2* o = reinterpret_cast<float2*>(
                        outp + (((size_t)b * HH + head) * TT + tt) * HS + d);
                    *o = make_float2(acc[i][j][2], acc[i][j][3]);
                }
            } else {
                const float b0 = bias[n], b1 = bias[n + 1];
                *reinterpret_cast<float2*>(out_direct + (size_t)r0 * CC + n) =
                    make_float2(acc[i][j][0] + b0, acc[i][j][1] + b1);
                *reinterpret_cast<float2*>(out_direct + (size_t)r1 * CC + n) =
                    make_float2(acc[i][j][2] + b0, acc[i][j][3] + b1);
            }
        }
    }
}

// ---------------------------------------------------------------------------
// Causal flash attention, fp32, HS=64 (known-good baseline kernel).
// ---------------------------------------------------------------------------
__global__ __launch_bounds__(256) void attn_kernel()
{
    const int qt = blockIdx.x;
    const int bh = blockIdx.y;
    const int q0 = qt * 64;

    const float* Q = g_q + (size_t)bh * TT * HS;
    const float* K = g_k + (size_t)bh * TT * HS;
    const float* V = g_v + (size_t)bh * TT * HS;

    extern __shared__ float sm[];
    float* Qs = sm;
    float* Ks = Qs + 64 * 65;
    float* Vs = Ks + 64 * 65;
    float* Ps = Vs + 64 * 65;

    const int t  = threadIdx.x;
    const int tx = t & 15;
    const int ty = t >> 4;

#pragma unroll
    for (int i = 0; i < 16; i++) {
        int idx = t + i * 256;
        int r = idx >> 6, d = idx & 63;
        Qs[r * 65 + d] = Q[(size_t)(q0 + r) * HS + d];
    }

    float m_run[4], l_run[4], O[4][4];
#pragma unroll
    for (int i = 0; i < 4; i++) {
        m_run[i] = -INFINITY;
        l_run[i] = 0.f;
#pragma unroll
        for (int j = 0; j < 4; j++) O[i][j] = 0.f;
    }

    const float scale = 0.125f;

    for (int jt = 0; jt <= qt; jt++) {
        const int k0 = jt * 64;
        __syncthreads();
#pragma unroll
        for (int i = 0; i < 16; i++) {
            int idx = t + i * 256;
            int r = idx >> 6, d = idx & 63;
            Ks[r * 65 + d] = K[(size_t)(k0 + r) * HS + d];
            Vs[r * 65 + d] = V[(size_t)(k0 + r) * HS + d];
        }
        __syncthreads();

        float S[4][4];
#pragma unroll
        for (int i = 0; i < 4; i++)
#pragma unroll
            for (int j = 0; j < 4; j++) S[i][j] = 0.f;

        for (int d = 0; d < 64; d++) {
            float a[4], b[4];
#pragma unroll
            for (int i = 0; i < 4; i++) a[i] = Qs[(ty * 4 + i) * 65 + d];
#pragma unroll
            for (int j = 0; j < 4; j++) b[j] = Ks[(tx * 4 + j) * 65 + d];
#pragma unroll
            for (int i = 0; i < 4; i++)
#pragma unroll
                for (int j = 0; j < 4; j++) S[i][j] += a[i] * b[j];
        }

        const bool diag = (jt == qt);
#pragma unroll
        for (int i = 0; i < 4; i++) {
#pragma unroll
            for (int j = 0; j < 4; j++) {
                S[i][j] *= scale;
                if (diag && (k0 + tx * 4 + j > q0 + ty * 4 + i))
                    S[i][j] = -INFINITY;
            }
        }

#pragma unroll
        for (int i = 0; i < 4; i++) {
            float mx = S[i][0];
#pragma unroll
            for (int j = 1; j < 4; j++) mx = fmaxf(mx, S[i][j]);
#pragma unroll
            for (int off = 8; off >= 1; off >>= 1)
                mx = fmaxf(mx, __shfl_xor_sync(0xffffffffu, mx, off));
            float mnew  = fmaxf(m_run[i], mx);
            float alpha = __expf(m_run[i] - mnew);
            m_run[i] = mnew;
            float ls = 0.f;
#pragma unroll
            for (int j = 0; j < 4; j++) {
                S[i][j] = __expf(S[i][j] - mnew);
                ls += S[i][j];
            }
#pragma unroll
            for (int off = 8; off >= 1; off >>= 1)
                ls += __shfl_xor_sync(0xffffffffu, ls, off);
            l_run[i] = l_run[i] * alpha + ls;
#pragma unroll
            for (int j = 0; j < 4; j++) O[i][j] *= alpha;
        }

#pragma unroll
        for (int i = 0; i < 4; i++)
#pragma unroll
            for (int j = 0; j < 4; j++)
                Ps[(ty * 4 + i) * 65 + tx * 4 + j] = S[i][j];
        __syncthreads();

        for (int s = 0; s < 64; s++) {
            float a[4], b[4];
#pragma unroll
            for (int i = 0; i < 4; i++) a[i] = Ps[(ty * 4 + i) * 65 + s];
#pragma unroll
            for (int j = 0; j < 4; j++) b[j] = Vs[s * 65 + tx * 4 + j];
#pragma unroll
            for (int i = 0; i < 4; i++)
#pragma unroll
                for (int j = 0; j < 4; j++) O[i][j] += a[i] * b[j];
        }
    }

    const int b = bh >> 4;
    const int h = bh & 15;
#pragma unroll
    for (int i = 0; i < 4; i++) {
        const float inv = 1.f / l_run[i];
        const int tt = q0 + ty * 4 + i;
        float* o = g_y + (((size_t)b * TT + tt) * HH + h) * HS + tx * 4;
#pragma unroll
        for (int j = 0; j < 4; j++) o[j] = O[i][j] * inv;
    }
}

// ---------------------------------------------------------------------------
extern "C" void kernel_launch(void* const* d_in, const int* in_sizes, int n_in,
                              void* d_out, int out_size)
{
    const float* x  = (const float*)d_in[0];
    const float* Wq = (const float*)d_in[1];
    const float* Wk = (const float*)d_in[2];
    const float* Wv = (const float*)d_in[3];
    const float* Wo = (const float*)d_in[4];
    const float* bo = (const float*)d_in[5];
    float* out = (float*)d_out;

    // Resolve device-global scratch symbols for cvt_split targets
    __nv_bfloat16 *xhi, *xlo, *yhi, *ylo, *wohi, *wolo;
    cudaGetSymbolAddress((void**)&xhi,  g_xhi);
    cudaGetSymbolAddress((void**)&xlo,  g_xlo);
    cudaGetSymbolAddress((void**)&yhi,  g_yhi);
    cudaGetSymbolAddress((void**)&ylo,  g_ylo);
    cudaGetSymbolAddress((void**)&wohi, g_wo_hi);
    cudaGetSymbolAddress((void**)&wolo, g_wo_lo);
    float* y;
    cudaGetSymbolAddress((void**)&y, g_y);

    // Prep: split x, W^T (q,k,v), Wo into hi/lo bf16
    cvt_split<<<(MM * CC) / (256 * 4), 256>>>(x, xhi, xlo);
    cvt_w_t<<<dim3(CC / 32, HS / 32, HH * 3), dim3(32, 8)>>>(Wq, Wk, Wv);
    cvt_split<<<(CC * CC) / (256 * 4), 256>>>(Wo, wohi, wolo);

    cudaFuncSetAttribute(hmma_gemm,
                         cudaFuncAttributeMaxDynamicSharedMemorySize, 65536);

    // QKV projections
    hmma_gemm<<<dim3(MM / 128, 8, 3), 256, 65536>>>(nullptr, nullptr, 0);

    // Flash attention (fp32)
    const size_t smem = 4 * 64 * 65 * sizeof(float);
    cudaFuncSetAttribute(attn_kernel,
                         cudaFuncAttributeMaxDynamicSharedMemorySize, (int)smem);
    attn_kernel<<<dim3(TT / 64, BB * HH), 256, smem>>>();

    // Split y, then output projection
    cvt_split<<<(MM * CC) / (256 * 4), 256>>>(y, yhi, ylo);
    hmma_gemm<<<dim3(MM / 128, 8, 1), 256, 65536>>>(bo, out, 1);
}

// round 9
// speedup vs baseline: 1.7145x; 1.1072x over previous
#include <cuda_runtime.h>
#include <cuda_bf16.h>
#include <math.h>
#include <cstdint>

// Problem constants
#define BB 4
#define TT 2048
#define CC 1024
#define HH 16
#define HS 64
#define MM (BB*TT)   // 8192

// ---------------------------------------------------------------------------
// Scratch (device globals: no allocations allowed)
// ---------------------------------------------------------------------------
// Split-bf16 inputs for the projection GEMMs
__device__ __nv_bfloat16 g_xhi[(size_t)MM*CC],  g_xlo[(size_t)MM*CC];
__device__ __nv_bfloat16 g_wt_hi[(size_t)3*HH*HS*CC], g_wt_lo[(size_t)3*HH*HS*CC]; // W^T: [which][h*HS+d][c]
__device__ __nv_bfloat16 g_wo_hi[(size_t)CC*CC], g_wo_lo[(size_t)CC*CC];           // [n][k]
// Attention operands (written by QKV GEMM epilogue)
__device__ __nv_bfloat16 g_qhi[(size_t)BB*HH*TT*HS], g_qlo[(size_t)BB*HH*TT*HS];   // [B,H,T,HS]
__device__ __nv_bfloat16 g_khi[(size_t)BB*HH*TT*HS], g_klo[(size_t)BB*HH*TT*HS];   // [B,H,T,HS]
__device__ __nv_bfloat16 g_vthi[(size_t)BB*HH*HS*TT], g_vtlo[(size_t)BB*HH*HS*TT]; // [B,H,HS,T] (V^T)
// Attention output (input to out-proj)
__device__ __nv_bfloat16 g_yhi[(size_t)MM*CC],  g_ylo[(size_t)MM*CC];              // [B,T,C]

// ---------------------------------------------------------------------------
// Warp-MMA helpers (compute_103-safe: sm_80+ mma.sync / ldmatrix only)
// ---------------------------------------------------------------------------
__device__ __forceinline__ uint32_t smem_u32(const void* p) {
    uint32_t a;
    asm("{ .reg .u64 t; cvta.to.shared.u64 t, %1; cvt.u32.u64 %0, t; }"
        : "=r"(a) : "l"(p));
    return a;
}

#define LDSM4(r, addr) \
    asm volatile("ldmatrix.sync.aligned.m8n8.x4.shared.b16 {%0,%1,%2,%3}, [%4];" \
        : "=r"((r)[0]), "=r"((r)[1]), "=r"((r)[2]), "=r"((r)[3]) : "r"(addr))

#define MMA_BF16(c, a, b) \
    asm volatile("mma.sync.aligned.m16n8k16.row.col.f32.bf16.bf16.f32 " \
        "{%0,%1,%2,%3}, {%4,%5,%6,%7}, {%8,%9}, {%0,%1,%2,%3};" \
        : "+f"((c)[0]), "+f"((c)[1]), "+f"((c)[2]), "+f"((c)[3]) \
        : "r"((a)[0]), "r"((a)[1]), "r"((a)[2]), "r"((a)[3]), \
          "r"((b)[0]), "r"((b)[1]))

__device__ __forceinline__ void split1(float v, __nv_bfloat16& h, __nv_bfloat16& l) {
    h = __float2bfloat16(v);
    l = __float2bfloat16(v - __bfloat162float(h));
}
__device__ __forceinline__ uint32_t packb(__nv_bfloat16 a, __nv_bfloat16 b) {
    return (uint32_t)__bfloat16_as_ushort(a) | ((uint32_t)__bfloat16_as_ushort(b) << 16);
}
// split two floats -> packed (hi, lo) bf16x2
__device__ __forceinline__ void split2(float v0, float v1, uint32_t& hi, uint32_t& lo) {
    __nv_bfloat16 h0, l0, h1, l1;
    split1(v0, h0, l0); split1(v1, h1, l1);
    hi = packb(h0, h1); lo = packb(l0, l1);
}

// ---------------------------------------------------------------------------
// Prep kernels: fp32 -> (hi, lo) bf16
// ---------------------------------------------------------------------------
__global__ __launch_bounds__(256) void cvt_split(const float* __restrict__ s,
                                                 __nv_bfloat16* __restrict__ hi,
                                                 __nv_bfloat16* __restrict__ lo)
{
    size_t i4 = (size_t)blockIdx.x * 256 + threadIdx.x;
    float4 v = reinterpret_cast<const float4*>(s)[i4];
    __nv_bfloat16 h[4], l[4];
    split1(v.x, h[0], l[0]); split1(v.y, h[1], l[1]);
    split1(v.z, h[2], l[2]); split1(v.w, h[3], l[3]);
    reinterpret_cast<uint2*>(hi)[i4] = make_uint2(packb(h[0], h[1]), packb(h[2], h[3]));
    reinterpret_cast<uint2*>(lo)[i4] = make_uint2(packb(l[0], l[1]), packb(l[2], l[3]));
}

// Transpose-convert W[h,c,d] -> wt[which][h*HS+d][c]
__global__ void cvt_w_t(const float* __restrict__ Wq,
                        const float* __restrict__ Wk,
                        const float* __restrict__ Wv)
{
    __shared__ float ts[32][33];
    const int which = blockIdx.z / HH;
    const int h     = blockIdx.z % HH;
    const float* W  = (which == 0) ? Wq : (which == 1) ? Wk : Wv;
    const int c0 = blockIdx.x * 32;
    const int d0 = blockIdx.y * 32;

    for (int i = threadIdx.y; i < 32; i += 8)
        ts[i][threadIdx.x] = W[((size_t)h * CC + c0 + i) * HS + d0 + threadIdx.x];
    __syncthreads();

    __nv_bfloat16* hi = g_wt_hi + (size_t)which * HH * HS * CC;
    __nv_bfloat16* lo = g_wt_lo + (size_t)which * HH * HS * CC;
    for (int i = threadIdx.y; i < 32; i += 8) {
        int d = d0 + i, c = c0 + threadIdx.x;
        float v = ts[threadIdx.x][i];
        __nv_bfloat16 vh, vl;
        split1(v, vh, vl);
        size_t o = (size_t)(h * HS + d) * CC + c;
        hi[o] = vh;
        lo[o] = vl;
    }
}

// ---------------------------------------------------------------------------
// Split-bf16 HMMA GEMM: D[128,128] = A[128,1024] * B[128,1024]^T
// mode 0: QKV. z=0 -> q (bf16 hi/lo [B,H,T,HS]); z=1 -> k (same);
//               z=2 -> v, stored TRANSPOSED as [B,H,HS,T] bf16 hi/lo.
// mode 1: out-proj: A = y split; B = Wo split; out -> d_out + bias (fp32).
// ---------------------------------------------------------------------------
__global__ __launch_bounds__(256) void hmma_gemm(const float* __restrict__ bias,
                                                 float* __restrict__ out_direct,
                                                 int mode)
{
    extern __shared__ unsigned char smem[];
    const uint32_t sb = smem_u32(smem);
    const int tid = threadIdx.x;
    const int wid = tid >> 5, lid = tid & 31;
    const int m0  = blockIdx.x * 128;
    const int warp_m = (wid & 1) * 64;
    const int warp_n = (wid >> 1) * 32;
    const int nbase  = blockIdx.y * 128;
    const int z = blockIdx.z;

    const __nv_bfloat16 *Ahi, *Alo, *Bhi, *Blo;
    if (mode == 0) {
        Ahi = g_xhi; Alo = g_xlo;
        const size_t wo = (size_t)z * HH * HS * CC + (size_t)nbase * CC;
        Bhi = g_wt_hi + wo; Blo = g_wt_lo + wo;
    } else {
        Ahi = g_yhi; Alo = g_ylo;
        Bhi = g_wo_hi + (size_t)nbase * CC;
        Blo = g_wo_lo + (size_t)nbase * CC;
    }

    float acc[4][4][4];
#pragma unroll
    for (int i = 0; i < 4; i++)
#pragma unroll
        for (int j = 0; j < 4; j++)
#pragma unroll
            for (int r = 0; r < 4; r++) acc[i][j][r] = 0.f;

    for (int c0 = 0; c0 < CC; c0 += 64) {
        __syncthreads();
#pragma unroll
        for (int it = 0; it < 4; it++) {
            int idx = tid + it * 256;
            int m = idx >> 3, kv = idx & 7;
            uint32_t soff = (uint32_t)(m * 128 + ((kv ^ (m & 7)) << 4));
            size_t ga = (size_t)(m0 + m) * CC + c0 + kv * 8;
            size_t gb = (size_t)m * CC + c0 + kv * 8;
            *reinterpret_cast<uint4*>(smem + soff)         = *reinterpret_cast<const uint4*>(Ahi + ga);
            *reinterpret_cast<uint4*>(smem + 16384 + soff) = *reinterpret_cast<const uint4*>(Alo + ga);
            *reinterpret_cast<uint4*>(smem + 32768 + soff) = *reinterpret_cast<const uint4*>(Bhi + gb);
            *reinterpret_cast<uint4*>(smem + 49152 + soff) = *reinterpret_cast<const uint4*>(Blo + gb);
        }
        __syncthreads();

#pragma unroll
        for (int ks = 0; ks < 4; ks++) {
            uint32_t aHi[4][4], aLo[4][4], bHi[4][2], bLo[4][2];
            const int kb = ks * 2 + (lid >> 4);
#pragma unroll
            for (int i = 0; i < 4; i++) {
                int row = warp_m + i * 16 + (lid & 15);
                uint32_t ad = sb + (uint32_t)(row * 128 + ((kb ^ (row & 7)) << 4));
                LDSM4(aHi[i], ad);
                LDSM4(aLo[i], ad + 16384);
            }
#pragma unroll
            for (int nb = 0; nb < 2; nb++) {
                int row = warp_n + nb * 16 + (lid & 15);
                uint32_t ad = sb + 32768 + (uint32_t)(row * 128 + ((kb ^ (row & 7)) << 4));
                uint32_t q[4];
                LDSM4(q, ad);
                bHi[nb*2][0] = q[0]; bHi[nb*2][1] = q[2];
                bHi[nb*2+1][0] = q[1]; bHi[nb*2+1][1] = q[3];
                LDSM4(q, ad + 16384);
                bLo[nb*2][0] = q[0]; bLo[nb*2][1] = q[2];
                bLo[nb*2+1][0] = q[1]; bLo[nb*2+1][1] = q[3];
            }
#pragma unroll
            for (int i = 0; i < 4; i++)
#pragma unroll
                for (int j = 0; j < 4; j++) {
                    MMA_BF16(acc[i][j], aHi[i], bHi[j]);
                    MMA_BF16(acc[i][j], aLo[i], bHi[j]);
                    MMA_BF16(acc[i][j], aHi[i], bLo[j]);
                }
        }
    }

    const int g = lid >> 2, t4 = lid & 3;

    if (mode == 1) {
#pragma unroll
        for (int i = 0; i < 4; i++)
#pragma unroll
            for (int j = 0; j < 4; j++) {
                const int n = nbase + warp_n + j * 8 + t4 * 2;
                const int r0 = m0 + warp_m + i * 16 + g;
                const float b0 = bias[n], b1 = bias[n + 1];
                *reinterpret_cast<float2*>(out_direct + (size_t)r0 * CC + n) =
                    make_float2(acc[i][j][0] + b0, acc[i][j][1] + b1);
                *reinterpret_cast<float2*>(out_direct + (size_t)(r0 + 8) * CC + n) =
                    make_float2(acc[i][j][2] + b0, acc[i][j][3] + b1);
            }
        return;
    }

    if (z != 2) {
        // q / k: split to bf16 hi/lo, store [B,H,T,HS]
        uint32_t* ohi = reinterpret_cast<uint32_t*>(z == 0 ? g_qhi : g_khi);
        uint32_t* olo = reinterpret_cast<uint32_t*>(z == 0 ? g_qlo : g_klo);
#pragma unroll
        for (int i = 0; i < 4; i++)
#pragma unroll
            for (int j = 0; j < 4; j++) {
                const int n = nbase + warp_n + j * 8 + t4 * 2;
                const int head = n >> 6, d = n & 63;
                const int r0 = m0 + warp_m + i * 16 + g;
                uint32_t hi, lo;
                {
                    int b = r0 >> 11, tt = r0 & (TT - 1);
                    size_t o = ((((size_t)b * HH + head) * TT + tt) * HS + d) >> 1;
                    split2(acc[i][j][0], acc[i][j][1], hi, lo);
                    ohi[o] = hi; olo[o] = lo;
                }
                {
                    int r1 = r0 + 8;
                    int b = r1 >> 11, tt = r1 & (TT - 1);
                    size_t o = ((((size_t)b * HH + head) * TT + tt) * HS + d) >> 1;
                    split2(acc[i][j][2], acc[i][j][3], hi, lo);
                    ohi[o] = hi; olo[o] = lo;
                }
            }
    } else {
        // v: stage fp32 tile in smem (XOR-swizzled), then write transposed [B,H,HS,T]
        __syncthreads();
        float* ps = reinterpret_cast<float*>(smem);   // [128][128], col ^= (row&31)
#pragma unroll
        for (int i = 0; i < 4; i++)
#pragma unroll
            for (int j = 0; j < 4; j++) {
                int m = warp_m + i * 16 + g;
                int n = warp_n + j * 8 + t4 * 2;
                ps[m * 128 + (n ^ (m & 31))]             = acc[i][j][0];
                ps[m * 128 + ((n + 1) ^ (m & 31))]       = acc[i][j][1];
                int m8 = m + 8;
                ps[m8 * 128 + (n ^ (m8 & 31))]           = acc[i][j][2];
                ps[m8 * 128 + ((n + 1) ^ (m8 & 31))]     = acc[i][j][3];
            }
        __syncthreads();
        uint32_t* ohi = reinterpret_cast<uint32_t*>(g_vthi);
        uint32_t* olo = reinterpret_cast<uint32_t*>(g_vtlo);
#pragma unroll
        for (int it = 0; it < 32; it++) {
            int u = tid + it * 256;               // 8192 pairs
            int dl = u >> 6;                      // local n (0..127)
            int tp = (u & 63) * 2;                // local m (even)
            float v0 = ps[tp * 128 + (dl ^ (tp & 31))];
            float v1 = ps[(tp + 1) * 128 + (dl ^ ((tp + 1) & 31))];
            uint32_t hi, lo;
            split2(v0, v1, hi, lo);
            int n = nbase + dl, head = n >> 6, d = n & 63;
            int tg = m0 + tp, b = tg >> 11, tt = tg & (TT - 1);
            size_t o = ((((size_t)b * HH + head) * HS + d) * TT + tt) >> 1;
            ohi[o] = hi; olo[o] = lo;
        }
    }
}

// ---------------------------------------------------------------------------
// Flash attention via split-bf16 HMMA. Br=128, Bc=64, HS=64.
// 8 warps x 16 q-rows. Q resident in smem; K / V^T tiles streamed.
// S = Q*K^T (3-split), softmax in fragments, P repacked in-register,
// O += P*V^T (3-split). Writes y as bf16 hi/lo [B,T,C].
// ---------------------------------------------------------------------------
#define AS_QHI 0u
#define AS_QLO 16384u
#define AS_KHI 32768u
#define AS_KLO 40960u
#define AS_VHI 49152u
#define AS_VLO 57344u

__global__ __launch_bounds__(256) void attn_mma()
{
    extern __shared__ unsigned char smem[];
    const uint32_t sb = smem_u32(smem);
    const int tid = threadIdx.x, wid = tid >> 5, lid = tid & 31;
    const int gid = lid >> 2, t4 = lid & 3;
    const int qt = gridDim.x - 1 - blockIdx.x;    // long blocks first
    const int bh = blockIdx.y;
    const int q0 = qt * 128;

    const __nv_bfloat16* Qhi = g_qhi + (size_t)bh * TT * HS;
    const __nv_bfloat16* Qlo = g_qlo + (size_t)bh * TT * HS;
    const __nv_bfloat16* Khi = g_khi + (size_t)bh * TT * HS;
    const __nv_bfloat16* Klo = g_klo + (size_t)bh * TT * HS;
    const __nv_bfloat16* Vhi = g_vthi + (size_t)bh * HS * TT;
    const __nv_bfloat16* Vlo = g_vtlo + (size_t)bh * HS * TT;

    // Load Q tile (128 rows x 64 bf16) hi/lo, swizzled
#pragma unroll
    for (int it = 0; it < 4; it++) {
        int idx = tid + it * 256;
        int m = idx >> 3, kv = idx & 7;
        uint32_t soff = (uint32_t)(m * 128 + ((kv ^ (m & 7)) << 4));
        size_t ga = (size_t)(q0 + m) * HS + kv * 8;
        *reinterpret_cast<uint4*>(smem + AS_QHI + soff) = *reinterpret_cast<const uint4*>(Qhi + ga);
        *reinterpret_cast<uint4*>(smem + AS_QLO + soff) = *reinterpret_cast<const uint4*>(Qlo + ga);
    }

    float O[8][4];
#pragma unroll
    for (int j = 0; j < 8; j++)
#pragma unroll
        for (int r = 0; r < 4; r++) O[j][r] = 0.f;
    float m0r = -1e30f, m1r = -1e30f, l0r = 0.f, l1r = 0.f;

    const int r0g = q0 + wid * 16 + gid;          // this thread's first q row
    const int jmax = 2 * qt + 1;

    for (int jt = 0; jt <= jmax; jt++) {
        const int k0 = jt * 64;
        __syncthreads();
#pragma unroll
        for (int it = 0; it < 2; it++) {
            int idx = tid + it * 256;
            int m = idx >> 3, kv = idx & 7;
            uint32_t soff = (uint32_t)(m * 128 + ((kv ^ (m & 7)) << 4));
            size_t ga = (size_t)(k0 + m) * HS + kv * 8;   // K rows: s
            *reinterpret_cast<uint4*>(smem + AS_KHI + soff) = *reinterpret_cast<const uint4*>(Khi + ga);
            *reinterpret_cast<uint4*>(smem + AS_KLO + soff) = *reinterpret_cast<const uint4*>(Klo + ga);
            size_t gv = (size_t)m * TT + k0 + kv * 8;     // V^T rows: d
            *reinterpret_cast<uint4*>(smem + AS_VHI + soff) = *reinterpret_cast<const uint4*>(Vhi + gv);
            *reinterpret_cast<uint4*>(smem + AS_VLO + soff) = *reinterpret_cast<const uint4*>(Vlo + gv);
        }
        __syncthreads();

        // ---- S = Q * K^T (16 x 64 per warp)
        float sa[8][4];
#pragma unroll
        for (int j = 0; j < 8; j++)
#pragma unroll
            for (int r = 0; r < 4; r++) sa[j][r] = 0.f;

#pragma unroll
        for (int ks = 0; ks < 4; ks++) {
            const int kb = ks * 2 + (lid >> 4);
            uint32_t aH[4], aL[4];
            {
                int row = wid * 16 + (lid & 15);
                uint32_t ad = sb + AS_QHI + (uint32_t)(row * 128 + ((kb ^ (row & 7)) << 4));
                LDSM4(aH, ad);
                LDSM4(aL, ad + 16384);
            }
            uint32_t bH[8][2], bL[8][2];
#pragma unroll
            for (int nb = 0; nb < 4; nb++) {
                int row = nb * 16 + (lid & 15);
                uint32_t ad = sb + AS_KHI + (uint32_t)(row * 128 + ((kb ^ (row & 7)) << 4));
                uint32_t q[4];
                LDSM4(q, ad);
                bH[nb*2][0] = q[0]; bH[nb*2][1] = q[2];
                bH[nb*2+1][0] = q[1]; bH[nb*2+1][1] = q[3];
                LDSM4(q, ad + 8192);
                bL[nb*2][0] = q[0]; bL[nb*2][1] = q[2];
                bL[nb*2+1][0] = q[1]; bL[nb*2+1][1] = q[3];
            }
#pragma unroll
            for (int j = 0; j < 8; j++) {
                MMA_BF16(sa[j], aH, bH[j]);
                MMA_BF16(sa[j], aL, bH[j]);
                MMA_BF16(sa[j], aH, bL[j]);
            }
        }

        // ---- scale + causal mask
#pragma unroll
        for (int j = 0; j < 8; j++)
#pragma unroll
            for (int r = 0; r < 4; r++) sa[j][r] *= 0.125f;

        if (k0 + 63 > q0 + wid * 16) {
#pragma unroll
            for (int j = 0; j < 8; j++) {
                int c = k0 + j * 8 + t4 * 2;
                if (c > r0g)         sa[j][0] = -1e30f;
                if (c + 1 > r0g)     sa[j][1] = -1e30f;
                if (c > r0g + 8)     sa[j][2] = -1e30f;
                if (c + 1 > r0g + 8) sa[j][3] = -1e30f;
            }
        }

        // ---- online softmax (rows r0g and r0g+8 per thread)
        float mx0 = -1e30f, mx1 = -1e30f;
#pragma unroll
        for (int j = 0; j < 8; j++) {
            mx0 = fmaxf(mx0, fmaxf(sa[j][0], sa[j][1]));
            mx1 = fmaxf(mx1, fmaxf(sa[j][2], sa[j][3]));
        }
        mx0 = fmaxf(mx0, __shfl_xor_sync(0xffffffffu, mx0, 1));
        mx0 = fmaxf(mx0, __shfl_xor_sync(0xffffffffu, mx0, 2));
        mx1 = fmaxf(mx1, __shfl_xor_sync(0xffffffffu, mx1, 1));
        mx1 = fmaxf(mx1, __shfl_xor_sync(0xffffffffu, mx1, 2));

        float mn0 = fmaxf(m0r, mx0), mn1 = fmaxf(m1r, mx1);
        float al0 = __expf(m0r - mn0), al1 = __expf(m1r - mn1);
        m0r = mn0; m1r = mn1;

        float ls0 = 0.f, ls1 = 0.f;
#pragma unroll
        for (int j = 0; j < 8; j++) {
            sa[j][0] = __expf(sa[j][0] - mn0);
            sa[j][1] = __expf(sa[j][1] - mn0);
            sa[j][2] = __expf(sa[j][2] - mn1);
            sa[j][3] = __expf(sa[j][3] - mn1);
            ls0 += sa[j][0] + sa[j][1];
            ls1 += sa[j][2] + sa[j][3];
        }
        ls0 += __shfl_xor_sync(0xffffffffu, ls0, 1);
        ls0 += __shfl_xor_sync(0xffffffffu, ls0, 2);
        ls1 += __shfl_xor_sync(0xffffffffu, ls1, 1);
        ls1 += __shfl_xor_sync(0xffffffffu, ls1, 2);
        l0r = l0r * al0 + ls0;
        l1r = l1r * al1 + ls1;

#pragma unroll
        for (int j = 0; j < 8; j++) {
            O[j][0] *= al0; O[j][1] *= al0;
            O[j][2] *= al1; O[j][3] *= al1;
        }

        // ---- O += P * V^T  (P repacked C-frag -> A-frag, hi/lo split)
#pragma unroll
        for (int kc = 0; kc < 4; kc++) {
            uint32_t pH[4], pL[4];
            split2(sa[2*kc][0],   sa[2*kc][1],   pH[0], pL[0]);
            split2(sa[2*kc][2],   sa[2*kc][3],   pH[1], pL[1]);
            split2(sa[2*kc+1][0], sa[2*kc+1][1], pH[2], pL[2]);
            split2(sa[2*kc+1][2], sa[2*kc+1][3], pH[3], pL[3]);

            const int kb = kc * 2 + (lid >> 4);
            uint32_t vH[8][2], vL[8][2];
#pragma unroll
            for (int nb = 0; nb < 4; nb++) {
                int row = nb * 16 + (lid & 15);
                uint32_t ad = sb + AS_VHI + (uint32_t)(row * 128 + ((kb ^ (row & 7)) << 4));
                uint32_t q[4];
                LDSM4(q, ad);
                vH[nb*2][0] = q[0]; vH[nb*2][1] = q[2];
                vH[nb*2+1][0] = q[1]; vH[nb*2+1][1] = q[3];
                LDSM4(q, ad + 8192);
                vL[nb*2][0] = q[0]; vL[nb*2][1] = q[2];
                vL[nb*2+1][0] = q[1]; vL[nb*2+1][1] = q[3];
            }
#pragma unroll
            for (int j = 0; j < 8; j++) {
                MMA_BF16(O[j], pH, vH[j]);
                MMA_BF16(O[j], pL, vH[j]);
                MMA_BF16(O[j], pH, vL[j]);
            }
        }
    }

    // ---- epilogue: y = O / l, bf16 hi/lo, layout [B,T,C]
    const int b = bh >> 4, h = bh & 15;
    const float inv0 = 1.f / l0r, inv1 = 1.f / l1r;
    uint32_t* yhi = reinterpret_cast<uint32_t*>(g_yhi);
    uint32_t* ylo = reinterpret_cast<uint32_t*>(g_ylo);
    const int t0 = r0g, t1 = r0g + 8;
#pragma unroll
    for (int j = 0; j < 8; j++) {
        int d = h * 64 + j * 8 + t4 * 2;
        uint32_t hi, lo;
        split2(O[j][0] * inv0, O[j][1] * inv0, hi, lo);
        size_t o0 = (((size_t)b * TT + t0) * CC + d) >> 1;
        yhi[o0] = hi; ylo[o0] = lo;
        split2(O[j][2] * inv1, O[j][3] * inv1, hi, lo);
        size_t o1 = (((size_t)b * TT + t1) * CC + d) >> 1;
        yhi[o1] = hi; ylo[o1] = lo;
    }
}

// ---------------------------------------------------------------------------
extern "C" void kernel_launch(void* const* d_in, const int* in_sizes, int n_in,
                              void* d_out, int out_size)
{
    const float* x  = (const float*)d_in[0];
    const float* Wq = (const float*)d_in[1];
    const float* Wk = (const float*)d_in[2];
    const float* Wv = (const float*)d_in[3];
    const float* Wo = (const float*)d_in[4];
    const float* bo = (const float*)d_in[5];
    float* out = (float*)d_out;

    __nv_bfloat16 *xhi, *xlo, *wohi, *wolo;
    cudaGetSymbolAddress((void**)&xhi,  g_xhi);
    cudaGetSymbolAddress((void**)&xlo,  g_xlo);
    cudaGetSymbolAddress((void**)&wohi, g_wo_hi);
    cudaGetSymbolAddress((void**)&wolo, g_wo_lo);

    // Prep: split x, W^T (q,k,v), Wo into hi/lo bf16
    cvt_split<<<(MM * CC) / (256 * 4), 256>>>(x, xhi, xlo);
    cvt_w_t<<<dim3(CC / 32, HS / 32, HH * 3), dim3(32, 8)>>>(Wq, Wk, Wv);
    cvt_split<<<(CC * CC) / (256 * 4), 256>>>(Wo, wohi, wolo);

    cudaFuncSetAttribute(hmma_gemm,
                         cudaFuncAttributeMaxDynamicSharedMemorySize, 65536);
    cudaFuncSetAttribute(attn_mma,
                         cudaFuncAttributeMaxDynamicSharedMemorySize, 65536);

    // QKV projections (epilogue emits bf16 hi/lo q, k, and transposed v)
    hmma_gemm<<<dim3(MM / 128, 8, 3), 256, 65536>>>(nullptr, nullptr, 0);

    // Flash attention on tensor cores
    attn_mma<<<dim3(TT / 128, BB * HH), 256, 65536>>>();

    // Output projection
    hmma_gemm<<<dim3(MM / 128, 8, 1), 256, 65536>>>(bo, out, 1);
}

// round 10
// speedup vs baseline: 3.0208x; 1.7619x over previous
#include <cuda_runtime.h>
#include <cuda_bf16.h>
#include <math.h>
#include <cstdint>

// Problem constants
#define BB 4
#define TT 2048
#define CC 1024
#define HH 16
#define HS 64
#define MM (BB*TT)   // 8192

// ---------------------------------------------------------------------------
// Scratch (device globals: no allocations allowed)
// ---------------------------------------------------------------------------
__device__ __nv_bfloat16 g_xhi[(size_t)MM*CC],  g_xlo[(size_t)MM*CC];
__device__ __nv_bfloat16 g_wt_hi[(size_t)3*HH*HS*CC], g_wt_lo[(size_t)3*HH*HS*CC]; // W^T: [which][h*HS+d][c]
__device__ __nv_bfloat16 g_wo_hi[(size_t)CC*CC], g_wo_lo[(size_t)CC*CC];           // [n][k]
__device__ __nv_bfloat16 g_qhi[(size_t)BB*HH*TT*HS], g_qlo[(size_t)BB*HH*TT*HS];   // [B,H,T,HS]
__device__ __nv_bfloat16 g_khi[(size_t)BB*HH*TT*HS], g_klo[(size_t)BB*HH*TT*HS];   // [B,H,T,HS]
__device__ __nv_bfloat16 g_vthi[(size_t)BB*HH*HS*TT], g_vtlo[(size_t)BB*HH*HS*TT]; // [B,H,HS,T] (V^T)
__device__ __nv_bfloat16 g_yhi[(size_t)MM*CC],  g_ylo[(size_t)MM*CC];              // [B,T,C]

// ---------------------------------------------------------------------------
// PTX helpers (compute_103-safe: sm_80+ mma.sync / ldmatrix / cp.async)
// ---------------------------------------------------------------------------
__device__ __forceinline__ uint32_t smem_u32(const void* p) {
    uint32_t a;
    asm("{ .reg .u64 t; cvta.to.shared.u64 t, %1; cvt.u32.u64 %0, t; }"
        : "=r"(a) : "l"(p));
    return a;
}

#define LDSM4(r, addr) \
    asm volatile("ldmatrix.sync.aligned.m8n8.x4.shared.b16 {%0,%1,%2,%3}, [%4];" \
        : "=r"((r)[0]), "=r"((r)[1]), "=r"((r)[2]), "=r"((r)[3]) : "r"(addr))

#define MMA_BF16(c, a, b) \
    asm volatile("mma.sync.aligned.m16n8k16.row.col.f32.bf16.bf16.f32 " \
        "{%0,%1,%2,%3}, {%4,%5,%6,%7}, {%8,%9}, {%0,%1,%2,%3};" \
        : "+f"((c)[0]), "+f"((c)[1]), "+f"((c)[2]), "+f"((c)[3]) \
        : "r"((a)[0]), "r"((a)[1]), "r"((a)[2]), "r"((a)[3]), \
          "r"((b)[0]), "r"((b)[1]))

#define CP_ASYNC16(saddr, gptr) \
    asm volatile("cp.async.cg.shared.global [%0], [%1], 16;" \
        :: "r"(saddr), "l"(gptr) : "memory")
#define CP_COMMIT() asm volatile("cp.async.commit_group;" ::: "memory")
#define CP_WAIT1()  asm volatile("cp.async.wait_group 1;" ::: "memory")
#define CP_WAIT0()  asm volatile("cp.async.wait_group 0;" ::: "memory")

__device__ __forceinline__ void split1(float v, __nv_bfloat16& h, __nv_bfloat16& l) {
    h = __float2bfloat16(v);
    l = __float2bfloat16(v - __bfloat162float(h));
}
__device__ __forceinline__ uint32_t packb(__nv_bfloat16 a, __nv_bfloat16 b) {
    return (uint32_t)__bfloat16_as_ushort(a) | ((uint32_t)__bfloat16_as_ushort(b) << 16);
}
__device__ __forceinline__ void split2(float v0, float v1, uint32_t& hi, uint32_t& lo) {
    __nv_bfloat16 h0, l0, h1, l1;
    split1(v0, h0, l0); split1(v1, h1, l1);
    hi = packb(h0, h1); lo = packb(l0, l1);
}

// ---------------------------------------------------------------------------
// Prep kernels: fp32 -> (hi, lo) bf16
// ---------------------------------------------------------------------------
__global__ __launch_bounds__(256) void cvt_split(const float* __restrict__ s,
                                                 __nv_bfloat16* __restrict__ hi,
                                                 __nv_bfloat16* __restrict__ lo)
{
    size_t i4 = (size_t)blockIdx.x * 256 + threadIdx.x;
    float4 v = reinterpret_cast<const float4*>(s)[i4];
    __nv_bfloat16 h[4], l[4];
    split1(v.x, h[0], l[0]); split1(v.y, h[1], l[1]);
    split1(v.z, h[2], l[2]); split1(v.w, h[3], l[3]);
    reinterpret_cast<uint2*>(hi)[i4] = make_uint2(packb(h[0], h[1]), packb(h[2], h[3]));
    reinterpret_cast<uint2*>(lo)[i4] = make_uint2(packb(l[0], l[1]), packb(l[2], l[3]));
}

__global__ void cvt_w_t(const float* __restrict__ Wq,
                        const float* __restrict__ Wk,
                        const float* __restrict__ Wv)
{
    __shared__ float ts[32][33];
    const int which = blockIdx.z / HH;
    const int h     = blockIdx.z % HH;
    const float* W  = (which == 0) ? Wq : (which == 1) ? Wk : Wv;
    const int c0 = blockIdx.x * 32;
    const int d0 = blockIdx.y * 32;

    for (int i = threadIdx.y; i < 32; i += 8)
        ts[i][threadIdx.x] = W[((size_t)h * CC + c0 + i) * HS + d0 + threadIdx.x];
    __syncthreads();

    __nv_bfloat16* hi = g_wt_hi + (size_t)which * HH * HS * CC;
    __nv_bfloat16* lo = g_wt_lo + (size_t)which * HH * HS * CC;
    for (int i = threadIdx.y; i < 32; i += 8) {
        int d = d0 + i, c = c0 + threadIdx.x;
        float v = ts[threadIdx.x][i];
        __nv_bfloat16 vh, vl;
        split1(v, vh, vl);
        size_t o = (size_t)(h * HS + d) * CC + c;
        hi[o] = vh;
        lo[o] = vl;
    }
}

// ---------------------------------------------------------------------------
// Split-bf16 HMMA GEMM with 2-stage cp.async pipeline.
// D[128,128] = A[128,1024] * B[128,1024]^T (Ahi*Bhi + Alo*Bhi + Ahi*Blo).
// Stage layout (per 64KB stage): AHI 0, ALO 16K, BHI 32K, BLO 48K.
// ---------------------------------------------------------------------------
__device__ __forceinline__ void gemm_stage_load(
    uint32_t sb, int stage, int tid, int m0,
    const __nv_bfloat16* __restrict__ Ahi, const __nv_bfloat16* __restrict__ Alo,
    const __nv_bfloat16* __restrict__ Bhi, const __nv_bfloat16* __restrict__ Blo,
    int c0)
{
    const uint32_t base = sb + (uint32_t)stage * 65536u;
#pragma unroll
    for (int it = 0; it < 4; it++) {
        int idx = tid + it * 256;
        int m = idx >> 3, kv = idx & 7;
        uint32_t soff = (uint32_t)(m * 128 + ((kv ^ (m & 7)) << 4));
        size_t ga = (size_t)(m0 + m) * CC + c0 + kv * 8;
        size_t gb = (size_t)m * CC + c0 + kv * 8;
        CP_ASYNC16(base + soff,          Ahi + ga);
        CP_ASYNC16(base + 16384 + soff,  Alo + ga);
        CP_ASYNC16(base + 32768 + soff,  Bhi + gb);
        CP_ASYNC16(base + 49152 + soff,  Blo + gb);
    }
}

__global__ __launch_bounds__(256) void hmma_gemm(const float* __restrict__ bias,
                                                 float* __restrict__ out_direct,
                                                 int mode)
{
    extern __shared__ unsigned char smem[];
    const uint32_t sb = smem_u32(smem);
    const int tid = threadIdx.x;
    const int wid = tid >> 5, lid = tid & 31;
    const int m0  = blockIdx.x * 128;
    const int warp_m = (wid & 1) * 64;
    const int warp_n = (wid >> 1) * 32;
    const int nbase  = blockIdx.y * 128;
    const int z = blockIdx.z;

    const __nv_bfloat16 *Ahi, *Alo, *Bhi, *Blo;
    if (mode == 0) {
        Ahi = g_xhi; Alo = g_xlo;
        const size_t wo = (size_t)z * HH * HS * CC + (size_t)nbase * CC;
        Bhi = g_wt_hi + wo; Blo = g_wt_lo + wo;
    } else {
        Ahi = g_yhi; Alo = g_ylo;
        Bhi = g_wo_hi + (size_t)nbase * CC;
        Blo = g_wo_lo + (size_t)nbase * CC;
    }

    float acc[4][4][4];
#pragma unroll
    for (int i = 0; i < 4; i++)
#pragma unroll
        for (int j = 0; j < 4; j++)
#pragma unroll
            for (int r = 0; r < 4; r++) acc[i][j][r] = 0.f;

    gemm_stage_load(sb, 0, tid, m0, Ahi, Alo, Bhi, Blo, 0);
    CP_COMMIT();

    for (int c0 = 0; c0 < CC; c0 += 64) {
        const int cur = (c0 >> 6) & 1;
        if (c0 + 64 < CC) {
            gemm_stage_load(sb, cur ^ 1, tid, m0, Ahi, Alo, Bhi, Blo, c0 + 64);
            CP_COMMIT();
            CP_WAIT1();
        } else {
            CP_WAIT0();
        }
        __syncthreads();

        const uint32_t stb = sb + (uint32_t)cur * 65536u;
#pragma unroll
        for (int ks = 0; ks < 4; ks++) {
            uint32_t aHi[4][4], aLo[4][4], bHi[4][2], bLo[4][2];
            const int kb = ks * 2 + (lid >> 4);
#pragma unroll
            for (int i = 0; i < 4; i++) {
                int row = warp_m + i * 16 + (lid & 15);
                uint32_t ad = stb + (uint32_t)(row * 128 + ((kb ^ (row & 7)) << 4));
                LDSM4(aHi[i], ad);
                LDSM4(aLo[i], ad + 16384);
            }
#pragma unroll
            for (int nb = 0; nb < 2; nb++) {
                int row = warp_n + nb * 16 + (lid & 15);
                uint32_t ad = stb + 32768 + (uint32_t)(row * 128 + ((kb ^ (row & 7)) << 4));
                uint32_t q[4];
                LDSM4(q, ad);
                bHi[nb*2][0] = q[0]; bHi[nb*2][1] = q[2];
                bHi[nb*2+1][0] = q[1]; bHi[nb*2+1][1] = q[3];
                LDSM4(q, ad + 16384);
                bLo[nb*2][0] = q[0]; bLo[nb*2][1] = q[2];
                bLo[nb*2+1][0] = q[1]; bLo[nb*2+1][1] = q[3];
            }
#pragma unroll
            for (int i = 0; i < 4; i++)
#pragma unroll
                for (int j = 0; j < 4; j++) {
                    MMA_BF16(acc[i][j], aHi[i], bHi[j]);
                    MMA_BF16(acc[i][j], aLo[i], bHi[j]);
                    MMA_BF16(acc[i][j], aHi[i], bLo[j]);
                }
        }
        __syncthreads();
    }

    const int g = lid >> 2, t4 = lid & 3;

    if (mode == 1) {
#pragma unroll
        for (int i = 0; i < 4; i++)
#pragma unroll
            for (int j = 0; j < 4; j++) {
                const int n = nbase + warp_n + j * 8 + t4 * 2;
                const int r0 = m0 + warp_m + i * 16 + g;
                const float b0 = bias[n], b1 = bias[n + 1];
                *reinterpret_cast<float2*>(out_direct + (size_t)r0 * CC + n) =
                    make_float2(acc[i][j][0] + b0, acc[i][j][1] + b1);
                *reinterpret_cast<float2*>(out_direct + (size_t)(r0 + 8) * CC + n) =
                    make_float2(acc[i][j][2] + b0, acc[i][j][3] + b1);
            }
        return;
    }

    if (z != 2) {
        uint32_t* ohi = reinterpret_cast<uint32_t*>(z == 0 ? g_qhi : g_khi);
        uint32_t* olo = reinterpret_cast<uint32_t*>(z == 0 ? g_qlo : g_klo);
#pragma unroll
        for (int i = 0; i < 4; i++)
#pragma unroll
            for (int j = 0; j < 4; j++) {
                const int n = nbase + warp_n + j * 8 + t4 * 2;
                const int head = n >> 6, d = n & 63;
                const int r0 = m0 + warp_m + i * 16 + g;
                uint32_t hi, lo;
                {
                    int b = r0 >> 11, tt = r0 & (TT - 1);
                    size_t o = ((((size_t)b * HH + head) * TT + tt) * HS + d) >> 1;
                    split2(acc[i][j][0], acc[i][j][1], hi, lo);
                    ohi[o] = hi; olo[o] = lo;
                }
                {
                    int r1 = r0 + 8;
                    int b = r1 >> 11, tt = r1 & (TT - 1);
                    size_t o = ((((size_t)b * HH + head) * TT + tt) * HS + d) >> 1;
                    split2(acc[i][j][2], acc[i][j][3], hi, lo);
                    ohi[o] = hi; olo[o] = lo;
                }
            }
    } else {
        // v: stage fp32 tile in smem (stage-0 area), write transposed [B,H,HS,T]
        __syncthreads();
        float* ps = reinterpret_cast<float*>(smem);   // [128][128], col ^= (row&31)
#pragma unroll
        for (int i = 0; i < 4; i++)
#pragma unroll
            for (int j = 0; j < 4; j++) {
                int m = warp_m + i * 16 + g;
                int n = warp_n + j * 8 + t4 * 2;
                ps[m * 128 + (n ^ (m & 31))]             = acc[i][j][0];
                ps[m * 128 + ((n + 1) ^ (m & 31))]       = acc[i][j][1];
                int m8 = m + 8;
                ps[m8 * 128 + (n ^ (m8 & 31))]           = acc[i][j][2];
                ps[m8 * 128 + ((n + 1) ^ (m8 & 31))]     = acc[i][j][3];
            }
        __syncthreads();
        uint32_t* ohi = reinterpret_cast<uint32_t*>(g_vthi);
        uint32_t* olo = reinterpret_cast<uint32_t*>(g_vtlo);
#pragma unroll
        for (int it = 0; it < 32; it++) {
            int u = tid + it * 256;
            int dl = u >> 6;
            int tp = (u & 63) * 2;
            float v0 = ps[tp * 128 + (dl ^ (tp & 31))];
            float v1 = ps[(tp + 1) * 128 + (dl ^ ((tp + 1) & 31))];
            uint32_t hi, lo;
            split2(v0, v1, hi, lo);
            int n = nbase + dl, head = n >> 6, d = n & 63;
            int tg = m0 + tp, b = tg >> 11, tt = tg & (TT - 1);
            size_t o = ((((size_t)b * HH + head) * HS + d) * TT + tt) >> 1;
            ohi[o] = hi; olo[o] = lo;
        }
    }
}

// ---------------------------------------------------------------------------
// Flash attention via split-bf16 HMMA, 2-stage cp.async K/V pipeline.
// SMEM: Q hi/lo resident [0,32K); K/V stages at 32K + s*32K
//   (per stage: KHI 0, KLO 8K, VHI 16K, VLO 24K). Total 96 KB.
// ---------------------------------------------------------------------------
__device__ __forceinline__ void attn_stage_load(
    uint32_t sb, int stage, int tid,
    const __nv_bfloat16* __restrict__ Khi, const __nv_bfloat16* __restrict__ Klo,
    const __nv_bfloat16* __restrict__ Vhi, const __nv_bfloat16* __restrict__ Vlo,
    int k0)
{
    const uint32_t base = sb + 32768u + (uint32_t)stage * 32768u;
#pragma unroll
    for (int it = 0; it < 2; it++) {
        int idx = tid + it * 256;
        int m = idx >> 3, kv = idx & 7;
        uint32_t soff = (uint32_t)(m * 128 + ((kv ^ (m & 7)) << 4));
        size_t ga = (size_t)(k0 + m) * HS + kv * 8;
        size_t gv = (size_t)m * TT + k0 + kv * 8;
        CP_ASYNC16(base + soff,          Khi + ga);
        CP_ASYNC16(base + 8192  + soff,  Klo + ga);
        CP_ASYNC16(base + 16384 + soff,  Vhi + gv);
        CP_ASYNC16(base + 24576 + soff,  Vlo + gv);
    }
}

__global__ __launch_bounds__(256) void attn_mma()
{
    extern __shared__ unsigned char smem[];
    const uint32_t sb = smem_u32(smem);
    const int tid = threadIdx.x, wid = tid >> 5, lid = tid & 31;
    const int gid = lid >> 2, t4 = lid & 3;
    const int qt = gridDim.x - 1 - blockIdx.x;    // long blocks first
    const int bh = blockIdx.y;
    const int q0 = qt * 128;

    const __nv_bfloat16* Qhi = g_qhi + (size_t)bh * TT * HS;
    const __nv_bfloat16* Qlo = g_qlo + (size_t)bh * TT * HS;
    const __nv_bfloat16* Khi = g_khi + (size_t)bh * TT * HS;
    const __nv_bfloat16* Klo = g_klo + (size_t)bh * TT * HS;
    const __nv_bfloat16* Vhi = g_vthi + (size_t)bh * HS * TT;
    const __nv_bfloat16* Vlo = g_vtlo + (size_t)bh * HS * TT;

    // Prologue: Q tile + K/V stage 0 via cp.async (one group)
#pragma unroll
    for (int it = 0; it < 4; it++) {
        int idx = tid + it * 256;
        int m = idx >> 3, kv = idx & 7;
        uint32_t soff = (uint32_t)(m * 128 + ((kv ^ (m & 7)) << 4));
        size_t ga = (size_t)(q0 + m) * HS + kv * 8;
        CP_ASYNC16(sb + soff,          Qhi + ga);
        CP_ASYNC16(sb + 16384 + soff,  Qlo + ga);
    }
    attn_stage_load(sb, 0, tid, Khi, Klo, Vhi, Vlo, 0);
    CP_COMMIT();

    float O[8][4];
#pragma unroll
    for (int j = 0; j < 8; j++)
#pragma unroll
        for (int r = 0; r < 4; r++) O[j][r] = 0.f;
    float m0r = -1e30f, m1r = -1e30f, l0r = 0.f, l1r = 0.f;

    const int r0g = q0 + wid * 16 + gid;
    const int jmax = 2 * qt + 1;

    for (int jt = 0; jt <= jmax; jt++) {
        const int k0 = jt * 64;
        if (jt < jmax) {
            attn_stage_load(sb, (jt + 1) & 1, tid, Khi, Klo, Vhi, Vlo, k0 + 64);
            CP_COMMIT();
            CP_WAIT1();
        } else {
            CP_WAIT0();
        }
        __syncthreads();

        const uint32_t kvb = sb + 32768u + (uint32_t)(jt & 1) * 32768u;

        // ---- S = Q * K^T (16 x 64 per warp)
        float sa[8][4];
#pragma unroll
        for (int j = 0; j < 8; j++)
#pragma unroll
            for (int r = 0; r < 4; r++) sa[j][r] = 0.f;

#pragma unroll
        for (int ks = 0; ks < 4; ks++) {
            const int kb = ks * 2 + (lid >> 4);
            uint32_t aH[4], aL[4];
            {
                int row = wid * 16 + (lid & 15);
                uint32_t ad = sb + (uint32_t)(row * 128 + ((kb ^ (row & 7)) << 4));
                LDSM4(aH, ad);
                LDSM4(aL, ad + 16384);
            }
            uint32_t bH[8][2], bL[8][2];
#pragma unroll
            for (int nb = 0; nb < 4; nb++) {
                int row = nb * 16 + (lid & 15);
                uint32_t ad = kvb + (uint32_t)(row * 128 + ((kb ^ (row & 7)) << 4));
                uint32_t q[4];
                LDSM4(q, ad);
                bH[nb*2][0] = q[0]; bH[nb*2][1] = q[2];
                bH[nb*2+1][0] = q[1]; bH[nb*2+1][1] = q[3];
                LDSM4(q, ad + 8192);
                bL[nb*2][0] = q[0]; bL[nb*2][1] = q[2];
                bL[nb*2+1][0] = q[1]; bL[nb*2+1][1] = q[3];
            }
#pragma unroll
            for (int j = 0; j < 8; j++) {
                MMA_BF16(sa[j], aH, bH[j]);
                MMA_BF16(sa[j], aL, bH[j]);
                MMA_BF16(sa[j], aH, bL[j]);
            }
        }

        // ---- scale + causal mask
#pragma unroll
        for (int j = 0; j < 8; j++)
#pragma unroll
            for (int r = 0; r < 4; r++) sa[j][r] *= 0.125f;

        if (k0 + 63 > q0 + wid * 16) {
#pragma unroll
            for (int j = 0; j < 8; j++) {
                int c = k0 + j * 8 + t4 * 2;
                if (c > r0g)         sa[j][0] = -1e30f;
                if (c + 1 > r0g)     sa[j][1] = -1e30f;
                if (c > r0g + 8)     sa[j][2] = -1e30f;
                if (c + 1 > r0g + 8) sa[j][3] = -1e30f;
            }
        }

        // ---- online softmax
        float mx0 = -1e30f, mx1 = -1e30f;
#pragma unroll
        for (int j = 0; j < 8; j++) {
            mx0 = fmaxf(mx0, fmaxf(sa[j][0], sa[j][1]));
            mx1 = fmaxf(mx1, fmaxf(sa[j][2], sa[j][3]));
        }
        mx0 = fmaxf(mx0, __shfl_xor_sync(0xffffffffu, mx0, 1));
        mx0 = fmaxf(mx0, __shfl_xor_sync(0xffffffffu, mx0, 2));
        mx1 = fmaxf(mx1, __shfl_xor_sync(0xffffffffu, mx1, 1));
        mx1 = fmaxf(mx1, __shfl_xor_sync(0xffffffffu, mx1, 2));

        float mn0 = fmaxf(m0r, mx0), mn1 = fmaxf(m1r, mx1);
        float al0 = __expf(m0r - mn0), al1 = __expf(m1r - mn1);
        m0r = mn0; m1r = mn1;

        float ls0 = 0.f, ls1 = 0.f;
#pragma unroll
        for (int j = 0; j < 8; j++) {
            sa[j][0] = __expf(sa[j][0] - mn0);
            sa[j][1] = __expf(sa[j][1] - mn0);
            sa[j][2] = __expf(sa[j][2] - mn1);
            sa[j][3] = __expf(sa[j][3] - mn1);
            ls0 += sa[j][0] + sa[j][1];
            ls1 += sa[j][2] + sa[j][3];
        }
        ls0 += __shfl_xor_sync(0xffffffffu, ls0, 1);
        ls0 += __shfl_xor_sync(0xffffffffu, ls0, 2);
        ls1 += __shfl_xor_sync(0xffffffffu, ls1, 1);
        ls1 += __shfl_xor_sync(0xffffffffu, ls1, 2);
        l0r = l0r * al0 + ls0;
        l1r = l1r * al1 + ls1;

#pragma unroll
        for (int j = 0; j < 8; j++) {
            O[j][0] *= al0; O[j][1] *= al0;
            O[j][2] *= al1; O[j][3] *= al1;
        }

        // ---- O += P * V^T  (P repacked C-frag -> A-frag, hi/lo split)
#pragma unroll
        for (int kc = 0; kc < 4; kc++) {
            uint32_t pH[4], pL[4];
            split2(sa[2*kc][0],   sa[2*kc][1],   pH[0], pL[0]);
            split2(sa[2*kc][2],   sa[2*kc][3],   pH[1], pL[1]);
            split2(sa[2*kc+1][0], sa[2*kc+1][1], pH[2], pL[2]);
            split2(sa[2*kc+1][2], sa[2*kc+1][3], pH[3], pL[3]);

            const int kb = kc * 2 + (lid >> 4);
            uint32_t vH[8][2], vL[8][2];
#pragma unroll
            for (int nb = 0; nb < 4; nb++) {
                int row = nb * 16 + (lid & 15);
                uint32_t ad = kvb + 16384 + (uint32_t)(row * 128 + ((kb ^ (row & 7)) << 4));
                uint32_t q[4];
                LDSM4(q, ad);
                vH[nb*2][0] = q[0]; vH[nb*2][1] = q[2];
                vH[nb*2+1][0] = q[1]; vH[nb*2+1][1] = q[3];
                LDSM4(q, ad + 8192);
                vL[nb*2][0] = q[0]; vL[nb*2][1] = q[2];
                vL[nb*2+1][0] = q[1]; vL[nb*2+1][1] = q[3];
            }
#pragma unroll
            for (int j = 0; j < 8; j++) {
                MMA_BF16(O[j], pH, vH[j]);
                MMA_BF16(O[j], pL, vH[j]);
                MMA_BF16(O[j], pH, vL[j]);
            }
        }
        __syncthreads();   // release this stage before it is overwritten
    }

    // ---- epilogue: y = O / l, bf16 hi/lo, layout [B,T,C]
    const int b = bh >> 4, h = bh & 15;
    const float inv0 = 1.f / l0r, inv1 = 1.f / l1r;
    uint32_t* yhi = reinterpret_cast<uint32_t*>(g_yhi);
    uint32_t* ylo = reinterpret_cast<uint32_t*>(g_ylo);
    const int t0 = r0g, t1 = r0g + 8;
#pragma unroll
    for (int j = 0; j < 8; j++) {
        int d = h * 64 + j * 8 + t4 * 2;
        uint32_t hi, lo;
        split2(O[j][0] * inv0, O[j][1] * inv0, hi, lo);
        size_t o0 = (((size_t)b * TT + t0) * CC + d) >> 1;
        yhi[o0] = hi; ylo[o0] = lo;
        split2(O[j][2] * inv1, O[j][3] * inv1, hi, lo);
        size_t o1 = (((size_t)b * TT + t1) * CC + d) >> 1;
        yhi[o1] = hi; ylo[o1] = lo;
    }
}

// ---------------------------------------------------------------------------
extern "C" void kernel_launch(void* const* d_in, const int* in_sizes, int n_in,
                              void* d_out, int out_size)
{
    const float* x  = (const float*)d_in[0];
    const float* Wq = (const float*)d_in[1];
    const float* Wk = (const float*)d_in[2];
    const float* Wv = (const float*)d_in[3];
    const float* Wo = (const float*)d_in[4];
    const float* bo = (const float*)d_in[5];
    float* out = (float*)d_out;

    __nv_bfloat16 *xhi, *xlo, *wohi, *wolo;
    cudaGetSymbolAddress((void**)&xhi,  g_xhi);
    cudaGetSymbolAddress((void**)&xlo,  g_xlo);
    cudaGetSymbolAddress((void**)&wohi, g_wo_hi);
    cudaGetSymbolAddress((void**)&wolo, g_wo_lo);

    // Prep: split x, W^T (q,k,v), Wo into hi/lo bf16
    cvt_split<<<(MM * CC) / (256 * 4), 256>>>(x, xhi, xlo);
    cvt_w_t<<<dim3(CC / 32, HS / 32, HH * 3), dim3(32, 8)>>>(Wq, Wk, Wv);
    cvt_split<<<(CC * CC) / (256 * 4), 256>>>(Wo, wohi, wolo);

    cudaFuncSetAttribute(hmma_gemm,
                         cudaFuncAttributeMaxDynamicSharedMemorySize, 131072);
    cudaFuncSetAttribute(attn_mma,
                         cudaFuncAttributeMaxDynamicSharedMemorySize, 98304);

    // QKV projections (epilogue emits bf16 hi/lo q, k, and transposed v)
    hmma_gemm<<<dim3(MM / 128, 8, 3), 256, 131072>>>(nullptr, nullptr, 0);

    // Flash attention on tensor cores
    attn_mma<<<dim3(TT / 128, BB * HH), 256, 98304>>>();

    // Output projection
    hmma_gemm<<<dim3(MM / 128, 8, 1), 256, 131072>>>(bo, out, 1);
}

// round 11
// speedup vs baseline: 3.2557x; 1.0778x over previous
#include <cuda_runtime.h>
#include <cuda_bf16.h>
#include <math.h>
#include <cstdint>

// Problem constants
#define BB 4
#define TT 2048
#define CC 1024
#define HH 16
#define HS 64
#define MM (BB*TT)   // 8192

// ---------------------------------------------------------------------------
// Scratch (device globals: no allocations allowed)
// ---------------------------------------------------------------------------
__device__ __nv_bfloat16 g_xhi[(size_t)MM*CC],  g_xlo[(size_t)MM*CC];
__device__ __nv_bfloat16 g_wt_hi[(size_t)3*HH*HS*CC], g_wt_lo[(size_t)3*HH*HS*CC]; // W^T: [which][h*HS+d][c]
__device__ __nv_bfloat16 g_wo_hi[(size_t)CC*CC], g_wo_lo[(size_t)CC*CC];           // [n][k]
__device__ __nv_bfloat16 g_qhi[(size_t)BB*HH*TT*HS], g_qlo[(size_t)BB*HH*TT*HS];   // [B,H,T,HS]
__device__ __nv_bfloat16 g_khi[(size_t)BB*HH*TT*HS], g_klo[(size_t)BB*HH*TT*HS];   // [B,H,T,HS]
__device__ __nv_bfloat16 g_vthi[(size_t)BB*HH*HS*TT], g_vtlo[(size_t)BB*HH*HS*TT]; // [B,H,HS,T] (V^T)
__device__ __nv_bfloat16 g_yhi[(size_t)MM*CC],  g_ylo[(size_t)MM*CC];              // [B,T,C]

// ---------------------------------------------------------------------------
// PTX helpers (compute_103-safe: sm_80+ mma.sync / ldmatrix / cp.async)
// ---------------------------------------------------------------------------
__device__ __forceinline__ uint32_t smem_u32(const void* p) {
    uint32_t a;
    asm("{ .reg .u64 t; cvta.to.shared.u64 t, %1; cvt.u32.u64 %0, t; }"
        : "=r"(a) : "l"(p));
    return a;
}

#define LDSM4(r, addr) \
    asm volatile("ldmatrix.sync.aligned.m8n8.x4.shared.b16 {%0,%1,%2,%3}, [%4];" \
        : "=r"((r)[0]), "=r"((r)[1]), "=r"((r)[2]), "=r"((r)[3]) : "r"(addr))

#define MMA_BF16(c, a, b) \
    asm volatile("mma.sync.aligned.m16n8k16.row.col.f32.bf16.bf16.f32 " \
        "{%0,%1,%2,%3}, {%4,%5,%6,%7}, {%8,%9}, {%0,%1,%2,%3};" \
        : "+f"((c)[0]), "+f"((c)[1]), "+f"((c)[2]), "+f"((c)[3]) \
        : "r"((a)[0]), "r"((a)[1]), "r"((a)[2]), "r"((a)[3]), \
          "r"((b)[0]), "r"((b)[1]))

#define CP_ASYNC16(saddr, gptr) \
    asm volatile("cp.async.cg.shared.global [%0], [%1], 16;" \
        :: "r"(saddr), "l"(gptr) : "memory")
#define CP_COMMIT() asm volatile("cp.async.commit_group;" ::: "memory")
#define CP_WAIT1()  asm volatile("cp.async.wait_group 1;" ::: "memory")
#define CP_WAIT0()  asm volatile("cp.async.wait_group 0;" ::: "memory")

__device__ __forceinline__ void split1(float v, __nv_bfloat16& h, __nv_bfloat16& l) {
    h = __float2bfloat16(v);
    l = __float2bfloat16(v - __bfloat162float(h));
}
__device__ __forceinline__ uint32_t packb(__nv_bfloat16 a, __nv_bfloat16 b) {
    return (uint32_t)__bfloat16_as_ushort(a) | ((uint32_t)__bfloat16_as_ushort(b) << 16);
}
__device__ __forceinline__ void split2(float v0, float v1, uint32_t& hi, uint32_t& lo) {
    __nv_bfloat16 h0, l0, h1, l1;
    split1(v0, h0, l0); split1(v1, h1, l1);
    hi = packb(h0, h1); lo = packb(l0, l1);
}

// ---------------------------------------------------------------------------
// Prep kernels: fp32 -> (hi, lo) bf16
// ---------------------------------------------------------------------------
__global__ __launch_bounds__(256) void cvt_split(const float* __restrict__ s,
                                                 __nv_bfloat16* __restrict__ hi,
                                                 __nv_bfloat16* __restrict__ lo)
{
    size_t i4 = (size_t)blockIdx.x * 256 + threadIdx.x;
    float4 v = reinterpret_cast<const float4*>(s)[i4];
    __nv_bfloat16 h[4], l[4];
    split1(v.x, h[0], l[0]); split1(v.y, h[1], l[1]);
    split1(v.z, h[2], l[2]); split1(v.w, h[3], l[3]);
    reinterpret_cast<uint2*>(hi)[i4] = make_uint2(packb(h[0], h[1]), packb(h[2], h[3]));
    reinterpret_cast<uint2*>(lo)[i4] = make_uint2(packb(l[0], l[1]), packb(l[2], l[3]));
}

__global__ void cvt_w_t(const float* __restrict__ Wq,
                        const float* __restrict__ Wk,
                        const float* __restrict__ Wv)
{
    __shared__ float ts[32][33];
    const int which = blockIdx.z / HH;
    const int h     = blockIdx.z % HH;
    const float* W  = (which == 0) ? Wq : (which == 1) ? Wk : Wv;
    const int c0 = blockIdx.x * 32;
    const int d0 = blockIdx.y * 32;

    for (int i = threadIdx.y; i < 32; i += 8)
        ts[i][threadIdx.x] = W[((size_t)h * CC + c0 + i) * HS + d0 + threadIdx.x];
    __syncthreads();

    __nv_bfloat16* hi = g_wt_hi + (size_t)which * HH * HS * CC;
    __nv_bfloat16* lo = g_wt_lo + (size_t)which * HH * HS * CC;
    for (int i = threadIdx.y; i < 32; i += 8) {
        int d = d0 + i, c = c0 + threadIdx.x;
        float v = ts[threadIdx.x][i];
        __nv_bfloat16 vh, vl;
        split1(v, vh, vl);
        size_t o = (size_t)(h * HS + d) * CC + c;
        hi[o] = vh;
        lo[o] = vl;
    }
}

// ---------------------------------------------------------------------------
// Split-bf16 HMMA GEMM, 2-stage cp.async pipeline, 2 CTAs/SM.
// Block tile 128(m) x 64(n) x 64(k). Warp tile 64x16 (8 warps, 2m x 4n).
// Stage (48KB): AHI 0, ALO 16K, BHI 32K, BLO 40K. 2 stages = 96KB smem.
// mode 0: QKV. z=0 -> q, z=1 -> k (bf16 hi/lo [B,H,T,HS]); z=2 -> v
//         stored TRANSPOSED [B,H,HS,T]. nbase = blockIdx.y*64 = one head.
// mode 1: out-proj: A = y split; B = Wo split; out -> d_out + bias (fp32).
// ---------------------------------------------------------------------------
#define GSTG 49152u

__device__ __forceinline__ void gemm_stage_load(
    uint32_t sb, int stage, int tid, int m0,
    const __nv_bfloat16* __restrict__ Ahi, const __nv_bfloat16* __restrict__ Alo,
    const __nv_bfloat16* __restrict__ Bhi, const __nv_bfloat16* __restrict__ Blo,
    int c0)
{
    const uint32_t base = sb + (uint32_t)stage * GSTG;
#pragma unroll
    for (int it = 0; it < 4; it++) {                 // A: 1024 uint4 per buffer
        int idx = tid + it * 256;
        int m = idx >> 3, kv = idx & 7;
        uint32_t soff = (uint32_t)(m * 128 + ((kv ^ (m & 7)) << 4));
        size_t ga = (size_t)(m0 + m) * CC + c0 + kv * 8;
        CP_ASYNC16(base + soff,          Ahi + ga);
        CP_ASYNC16(base + 16384 + soff,  Alo + ga);
    }
#pragma unroll
    for (int it = 0; it < 2; it++) {                 // B: 512 uint4 per buffer
        int idx = tid + it * 256;
        int n = idx >> 3, kv = idx & 7;
        uint32_t soff = (uint32_t)(n * 128 + ((kv ^ (n & 7)) << 4));
        size_t gb = (size_t)n * CC + c0 + kv * 8;
        CP_ASYNC16(base + 32768 + soff,  Bhi + gb);
        CP_ASYNC16(base + 40960 + soff,  Blo + gb);
    }
}

__global__ __launch_bounds__(256, 2) void hmma_gemm(const float* __restrict__ bias,
                                                    float* __restrict__ out_direct,
                                                    int mode)
{
    extern __shared__ unsigned char smem[];
    const uint32_t sb = smem_u32(smem);
    const int tid = threadIdx.x;
    const int wid = tid >> 5, lid = tid & 31;
    const int m0  = blockIdx.x * 128;
    const int warp_m = (wid & 1) * 64;
    const int warp_n = (wid >> 1) * 16;
    const int nbase  = blockIdx.y * 64;
    const int z = blockIdx.z;

    const __nv_bfloat16 *Ahi, *Alo, *Bhi, *Blo;
    if (mode == 0) {
        Ahi = g_xhi; Alo = g_xlo;
        const size_t wo = (size_t)z * HH * HS * CC + (size_t)nbase * CC;
        Bhi = g_wt_hi + wo; Blo = g_wt_lo + wo;
    } else {
        Ahi = g_yhi; Alo = g_ylo;
        Bhi = g_wo_hi + (size_t)nbase * CC;
        Blo = g_wo_lo + (size_t)nbase * CC;
    }

    float acc[4][2][4];
#pragma unroll
    for (int i = 0; i < 4; i++)
#pragma unroll
        for (int j = 0; j < 2; j++)
#pragma unroll
            for (int r = 0; r < 4; r++) acc[i][j][r] = 0.f;

    gemm_stage_load(sb, 0, tid, m0, Ahi, Alo, Bhi, Blo, 0);
    CP_COMMIT();

    for (int c0 = 0; c0 < CC; c0 += 64) {
        const int cur = (c0 >> 6) & 1;
        if (c0 + 64 < CC) {
            gemm_stage_load(sb, cur ^ 1, tid, m0, Ahi, Alo, Bhi, Blo, c0 + 64);
            CP_COMMIT();
            CP_WAIT1();
        } else {
            CP_WAIT0();
        }
        __syncthreads();

        const uint32_t stb = sb + (uint32_t)cur * GSTG;
#pragma unroll
        for (int ks = 0; ks < 4; ks++) {
            const int kb = ks * 2 + (lid >> 4);
            uint32_t aHi[4][4], aLo[4][4], bHi[2][2], bLo[2][2];
#pragma unroll
            for (int i = 0; i < 4; i++) {
                int row = warp_m + i * 16 + (lid & 15);
                uint32_t ad = stb + (uint32_t)(row * 128 + ((kb ^ (row & 7)) << 4));
                LDSM4(aHi[i], ad);
                LDSM4(aLo[i], ad + 16384);
            }
            {
                int row = warp_n + (lid & 15);
                uint32_t ad = stb + 32768 + (uint32_t)(row * 128 + ((kb ^ (row & 7)) << 4));
                uint32_t q[4];
                LDSM4(q, ad);
                bHi[0][0] = q[0]; bHi[0][1] = q[2];
                bHi[1][0] = q[1]; bHi[1][1] = q[3];
                LDSM4(q, ad + 8192);
                bLo[0][0] = q[0]; bLo[0][1] = q[2];
                bLo[1][0] = q[1]; bLo[1][1] = q[3];
            }
#pragma unroll
            for (int i = 0; i < 4; i++)
#pragma unroll
                for (int j = 0; j < 2; j++) {
                    MMA_BF16(acc[i][j], aHi[i], bHi[j]);
                    MMA_BF16(acc[i][j], aLo[i], bHi[j]);
                    MMA_BF16(acc[i][j], aHi[i], bLo[j]);
                }
        }
        __syncthreads();
    }

    const int g = lid >> 2, t4 = lid & 3;

    if (mode == 1) {
#pragma unroll
        for (int i = 0; i < 4; i++)
#pragma unroll
            for (int j = 0; j < 2; j++) {
                const int n = nbase + warp_n + j * 8 + t4 * 2;
                const int r0 = m0 + warp_m + i * 16 + g;
                const float b0 = bias[n], b1 = bias[n + 1];
                *reinterpret_cast<float2*>(out_direct + (size_t)r0 * CC + n) =
                    make_float2(acc[i][j][0] + b0, acc[i][j][1] + b1);
                *reinterpret_cast<float2*>(out_direct + (size_t)(r0 + 8) * CC + n) =
                    make_float2(acc[i][j][2] + b0, acc[i][j][3] + b1);
            }
        return;
    }

    const int head = blockIdx.y;   // BN == HS == 64

    if (z != 2) {
        uint32_t* ohi = reinterpret_cast<uint32_t*>(z == 0 ? g_qhi : g_khi);
        uint32_t* olo = reinterpret_cast<uint32_t*>(z == 0 ? g_qlo : g_klo);
#pragma unroll
        for (int i = 0; i < 4; i++)
#pragma unroll
            for (int j = 0; j < 2; j++) {
                const int d = warp_n + j * 8 + t4 * 2;
                const int r0 = m0 + warp_m + i * 16 + g;
                uint32_t hi, lo;
                {
                    int b = r0 >> 11, tt = r0 & (TT - 1);
                    size_t o = ((((size_t)b * HH + head) * TT + tt) * HS + d) >> 1;
                    split2(acc[i][j][0], acc[i][j][1], hi, lo);
                    ohi[o] = hi; olo[o] = lo;
                }
                {
                    int r1 = r0 + 8;
                    int b = r1 >> 11, tt = r1 & (TT - 1);
                    size_t o = ((((size_t)b * HH + head) * TT + tt) * HS + d) >> 1;
                    split2(acc[i][j][2], acc[i][j][3], hi, lo);
                    ohi[o] = hi; olo[o] = lo;
                }
            }
    } else {
        // v: stage fp32 tile (128 x 64) in smem, write transposed [B,H,HS,T]
        __syncthreads();
        float* ps = reinterpret_cast<float*>(smem);   // [128][64], col ^= (row&31)
#pragma unroll
        for (int i = 0; i < 4; i++)
#pragma unroll
            for (int j = 0; j < 2; j++) {
                int m = warp_m + i * 16 + g;
                int n = warp_n + j * 8 + t4 * 2;
                ps[m * 64 + (n ^ (m & 31))]            = acc[i][j][0];
                ps[m * 64 + ((n + 1) ^ (m & 31))]      = acc[i][j][1];
                int m8 = m + 8;
                ps[m8 * 64 + (n ^ (m8 & 31))]          = acc[i][j][2];
                ps[m8 * 64 + ((n + 1) ^ (m8 & 31))]    = acc[i][j][3];
            }
        __syncthreads();
        uint32_t* ohi = reinterpret_cast<uint32_t*>(g_vthi);
        uint32_t* olo = reinterpret_cast<uint32_t*>(g_vtlo);
#pragma unroll
        for (int it = 0; it < 16; it++) {             // 4096 (d, t-pair) pairs
            int u = tid + it * 256;
            int dl = u >> 6;                          // 0..63 (d)
            int tp = (u & 63) * 2;                    // local m (even)
            float v0 = ps[tp * 64 + (dl ^ (tp & 31))];
            float v1 = ps[(tp + 1) * 64 + (dl ^ ((tp + 1) & 31))];
            uint32_t hi, lo;
            split2(v0, v1, hi, lo);
            int tg = m0 + tp, b = tg >> 11, tt = tg & (TT - 1);
            size_t o = ((((size_t)b * HH + head) * HS + dl) * TT + tt) >> 1;
            ohi[o] = hi; olo[o] = lo;
        }
    }
}

// ---------------------------------------------------------------------------
// Flash attention via split-bf16 HMMA, 2-stage cp.async K/V pipeline.
// (unchanged from R10)
// SMEM: Q hi/lo resident [0,32K); K/V stages at 32K + s*32K
//   (per stage: KHI 0, KLO 8K, VHI 16K, VLO 24K). Total 96 KB.
// ---------------------------------------------------------------------------
__device__ __forceinline__ void attn_stage_load(
    uint32_t sb, int stage, int tid,
    const __nv_bfloat16* __restrict__ Khi, const __nv_bfloat16* __restrict__ Klo,
    const __nv_bfloat16* __restrict__ Vhi, const __nv_bfloat16* __restrict__ Vlo,
    int k0)
{
    const uint32_t base = sb + 32768u + (uint32_t)stage * 32768u;
#pragma unroll
    for (int it = 0; it < 2; it++) {
        int idx = tid + it * 256;
        int m = idx >> 3, kv = idx & 7;
        uint32_t soff = (uint32_t)(m * 128 + ((kv ^ (m & 7)) << 4));
        size_t ga = (size_t)(k0 + m) * HS + kv * 8;
        size_t gv = (size_t)m * TT + k0 + kv * 8;
        CP_ASYNC16(base + soff,          Khi + ga);
        CP_ASYNC16(base + 8192  + soff,  Klo + ga);
        CP_ASYNC16(base + 16384 + soff,  Vhi + gv);
        CP_ASYNC16(base + 24576 + soff,  Vlo + gv);
    }
}

__global__ __launch_bounds__(256) void attn_mma()
{
    extern __shared__ unsigned char smem[];
    const uint32_t sb = smem_u32(smem);
    const int tid = threadIdx.x, wid = tid >> 5, lid = tid & 31;
    const int gid = lid >> 2, t4 = lid & 3;
    const int qt = gridDim.x - 1 - blockIdx.x;    // long blocks first
    const int bh = blockIdx.y;
    const int q0 = qt * 128;

    const __nv_bfloat16* Qhi = g_qhi + (size_t)bh * TT * HS;
    const __nv_bfloat16* Qlo = g_qlo + (size_t)bh * TT * HS;
    const __nv_bfloat16* Khi = g_khi + (size_t)bh * TT * HS;
    const __nv_bfloat16* Klo = g_klo + (size_t)bh * TT * HS;
    const __nv_bfloat16* Vhi = g_vthi + (size_t)bh * HS * TT;
    const __nv_bfloat16* Vlo = g_vtlo + (size_t)bh * HS * TT;

    // Prologue: Q tile + K/V stage 0 via cp.async (one group)
#pragma unroll
    for (int it = 0; it < 4; it++) {
        int idx = tid + it * 256;
        int m = idx >> 3, kv = idx & 7;
        uint32_t soff = (uint32_t)(m * 128 + ((kv ^ (m & 7)) << 4));
        size_t ga = (size_t)(q0 + m) * HS + kv * 8;
        CP_ASYNC16(sb + soff,          Qhi + ga);
        CP_ASYNC16(sb + 16384 + soff,  Qlo + ga);
    }
    attn_stage_load(sb, 0, tid, Khi, Klo, Vhi, Vlo, 0);
    CP_COMMIT();

    float O[8][4];
#pragma unroll
    for (int j = 0; j < 8; j++)
#pragma unroll
        for (int r = 0; r < 4; r++) O[j][r] = 0.f;
    float m0r = -1e30f, m1r = -1e30f, l0r = 0.f, l1r = 0.f;

    const int r0g = q0 + wid * 16 + gid;
    const int jmax = 2 * qt + 1;

    for (int jt = 0; jt <= jmax; jt++) {
        const int k0 = jt * 64;
        if (jt < jmax) {
            attn_stage_load(sb, (jt + 1) & 1, tid, Khi, Klo, Vhi, Vlo, k0 + 64);
            CP_COMMIT();
            CP_WAIT1();
        } else {
            CP_WAIT0();
        }
        __syncthreads();

        const uint32_t kvb = sb + 32768u + (uint32_t)(jt & 1) * 32768u;

        // ---- S = Q * K^T (16 x 64 per warp)
        float sa[8][4];
#pragma unroll
        for (int j = 0; j < 8; j++)
#pragma unroll
            for (int r = 0; r < 4; r++) sa[j][r] = 0.f;

#pragma unroll
        for (int ks = 0; ks < 4; ks++) {
            const int kb = ks * 2 + (lid >> 4);
            uint32_t aH[4], aL[4];
            {
                int row = wid * 16 + (lid & 15);
                uint32_t ad = sb + (uint32_t)(row * 128 + ((kb ^ (row & 7)) << 4));
                LDSM4(aH, ad);
                LDSM4(aL, ad + 16384);
            }
            uint32_t bH[8][2], bL[8][2];
#pragma unroll
            for (int nb = 0; nb < 4; nb++) {
                int row = nb * 16 + (lid & 15);
                uint32_t ad = kvb + (uint32_t)(row * 128 + ((kb ^ (row & 7)) << 4));
                uint32_t q[4];
                LDSM4(q, ad);
                bH[nb*2][0] = q[0]; bH[nb*2][1] = q[2];
                bH[nb*2+1][0] = q[1]; bH[nb*2+1][1] = q[3];
                LDSM4(q, ad + 8192);
                bL[nb*2][0] = q[0]; bL[nb*2][1] = q[2];
                bL[nb*2+1][0] = q[1]; bL[nb*2+1][1] = q[3];
            }
#pragma unroll
            for (int j = 0; j < 8; j++) {
                MMA_BF16(sa[j], aH, bH[j]);
                MMA_BF16(sa[j], aL, bH[j]);
                MMA_BF16(sa[j], aH, bL[j]);
            }
        }

        // ---- scale + causal mask
#pragma unroll
        for (int j = 0; j < 8; j++)
#pragma unroll
            for (int r = 0; r < 4; r++) sa[j][r] *= 0.125f;

        if (k0 + 63 > q0 + wid * 16) {
#pragma unroll
            for (int j = 0; j < 8; j++) {
                int c = k0 + j * 8 + t4 * 2;
                if (c > r0g)         sa[j][0] = -1e30f;
                if (c + 1 > r0g)     sa[j][1] = -1e30f;
                if (c > r0g + 8)     sa[j][2] = -1e30f;
                if (c + 1 > r0g + 8) sa[j][3] = -1e30f;
            }
        }

        // ---- online softmax
        float mx0 = -1e30f, mx1 = -1e30f;
#pragma unroll
        for (int j = 0; j < 8; j++) {
            mx0 = fmaxf(mx0, fmaxf(sa[j][0], sa[j][1]));
            mx1 = fmaxf(mx1, fmaxf(sa[j][2], sa[j][3]));
        }
        mx0 = fmaxf(mx0, __shfl_xor_sync(0xffffffffu, mx0, 1));
        mx0 = fmaxf(mx0, __shfl_xor_sync(0xffffffffu, mx0, 2));
        mx1 = fmaxf(mx1, __shfl_xor_sync(0xffffffffu, mx1, 1));
        mx1 = fmaxf(mx1, __shfl_xor_sync(0xffffffffu, mx1, 2));

        float mn0 = fmaxf(m0r, mx0), mn1 = fmaxf(m1r, mx1);
        float al0 = __expf(m0r - mn0), al1 = __expf(m1r - mn1);
        m0r = mn0; m1r = mn1;

        float ls0 = 0.f, ls1 = 0.f;
#pragma unroll
        for (int j = 0; j < 8; j++) {
            sa[j][0] = __expf(sa[j][0] - mn0);
            sa[j][1] = __expf(sa[j][1] - mn0);
            sa[j][2] = __expf(sa[j][2] - mn1);
            sa[j][3] = __expf(sa[j][3] - mn1);
            ls0 += sa[j][0] + sa[j][1];
            ls1 += sa[j][2] + sa[j][3];
        }
        ls0 += __shfl_xor_sync(0xffffffffu, ls0, 1);
        ls0 += __shfl_xor_sync(0xffffffffu, ls0, 2);
        ls1 += __shfl_xor_sync(0xffffffffu, ls1, 1);
        ls1 += __shfl_xor_sync(0xffffffffu, ls1, 2);
        l0r = l0r * al0 + ls0;
        l1r = l1r * al1 + ls1;

#pragma unroll
        for (int j = 0; j < 8; j++) {
            O[j][0] *= al0; O[j][1] *= al0;
            O[j][2] *= al1; O[j][3] *= al1;
        }

        // ---- O += P * V^T  (P repacked C-frag -> A-frag, hi/lo split)
#pragma unroll
        for (int kc = 0; kc < 4; kc++) {
            uint32_t pH[4], pL[4];
            split2(sa[2*kc][0],   sa[2*kc][1],   pH[0], pL[0]);
            split2(sa[2*kc][2],   sa[2*kc][3],   pH[1], pL[1]);
            split2(sa[2*kc+1][0], sa[2*kc+1][1], pH[2], pL[2]);
            split2(sa[2*kc+1][2], sa[2*kc+1][3], pH[3], pL[3]);

            const int kb = kc * 2 + (lid >> 4);
            uint32_t vH[8][2], vL[8][2];
#pragma unroll
            for (int nb = 0; nb < 4; nb++) {
                int row = nb * 16 + (lid & 15);
                uint32_t ad = kvb + 16384 + (uint32_t)(row * 128 + ((kb ^ (row & 7)) << 4));
                uint32_t q[4];
                LDSM4(q, ad);
                vH[nb*2][0] = q[0]; vH[nb*2][1] = q[2];
                vH[nb*2+1][0] = q[1]; vH[nb*2+1][1] = q[3];
                LDSM4(q, ad + 8192);
                vL[nb*2][0] = q[0]; vL[nb*2][1] = q[2];
                vL[nb*2+1][0] = q[1]; vL[nb*2+1][1] = q[3];
            }
#pragma unroll
            for (int j = 0; j < 8; j++) {
                MMA_BF16(O[j], pH, vH[j]);
                MMA_BF16(O[j], pL, vH[j]);
                MMA_BF16(O[j], pH, vL[j]);
            }
        }
        __syncthreads();   // release this stage before it is overwritten
    }

    // ---- epilogue: y = O / l, bf16 hi/lo, layout [B,T,C]
    const int b = bh >> 4, h = bh & 15;
    const float inv0 = 1.f / l0r, inv1 = 1.f / l1r;
    uint32_t* yhi = reinterpret_cast<uint32_t*>(g_yhi);
    uint32_t* ylo = reinterpret_cast<uint32_t*>(g_ylo);
    const int t0 = r0g, t1 = r0g + 8;
#pragma unroll
    for (int j = 0; j < 8; j++) {
        int d = h * 64 + j * 8 + t4 * 2;
        uint32_t hi, lo;
        split2(O[j][0] * inv0, O[j][1] * inv0, hi, lo);
        size_t o0 = (((size_t)b * TT + t0) * CC + d) >> 1;
        yhi[o0] = hi; ylo[o0] = lo;
        split2(O[j][2] * inv1, O[j][3] * inv1, hi, lo);
        size_t o1 = (((size_t)b * TT + t1) * CC + d) >> 1;
        yhi[o1] = hi; ylo[o1] = lo;
    }
}

// ---------------------------------------------------------------------------
extern "C" void kernel_launch(void* const* d_in, const int* in_sizes, int n_in,
                              void* d_out, int out_size)
{
    const float* x  = (const float*)d_in[0];
    const float* Wq = (const float*)d_in[1];
    const float* Wk = (const float*)d_in[2];
    const float* Wv = (const float*)d_in[3];
    const float* Wo = (const float*)d_in[4];
    const float* bo = (const float*)d_in[5];
    float* out = (float*)d_out;

    __nv_bfloat16 *xhi, *xlo, *wohi, *wolo;
    cudaGetSymbolAddress((void**)&xhi,  g_xhi);
    cudaGetSymbolAddress((void**)&xlo,  g_xlo);
    cudaGetSymbolAddress((void**)&wohi, g_wo_hi);
    cudaGetSymbolAddress((void**)&wolo, g_wo_lo);

    // Prep: split x, W^T (q,k,v), Wo into hi/lo bf16
    cvt_split<<<(MM * CC) / (256 * 4), 256>>>(x, xhi, xlo);
    cvt_w_t<<<dim3(CC / 32, HS / 32, HH * 3), dim3(32, 8)>>>(Wq, Wk, Wv);
    cvt_split<<<(CC * CC) / (256 * 4), 256>>>(Wo, wohi, wolo);

    cudaFuncSetAttribute(hmma_gemm,
                         cudaFuncAttributeMaxDynamicSharedMemorySize, 98304);
    cudaFuncSetAttribute(attn_mma,
                         cudaFuncAttributeMaxDynamicSharedMemorySize, 98304);

    // QKV projections (epilogue emits bf16 hi/lo q, k, and transposed v)
    hmma_gemm<<<dim3(MM / 128, CC / 64, 3), 256, 98304>>>(nullptr, nullptr, 0);

    // Flash attention on tensor cores
    attn_mma<<<dim3(TT / 128, BB * HH), 256, 98304>>>();

    // Output projection
    hmma_gemm<<<dim3(MM / 128, CC / 64, 1), 256, 98304>>>(bo, out, 1);
}

// round 13
// speedup vs baseline: 3.2899x; 1.0105x over previous
#include <cuda_runtime.h>
#include <cuda_bf16.h>
#include <math.h>
#include <cstdint>

// Problem constants
#define BB 4
#define TT 2048
#define CC 1024
#define HH 16
#define HS 64
#define MM (BB*TT)   // 8192

// ---------------------------------------------------------------------------
// Scratch (device globals: no allocations allowed)
// ---------------------------------------------------------------------------
__device__ __nv_bfloat16 g_xhi[(size_t)MM*CC],  g_xlo[(size_t)MM*CC];
__device__ __nv_bfloat16 g_wt_hi[(size_t)3*HH*HS*CC], g_wt_lo[(size_t)3*HH*HS*CC]; // W^T: [which][h*HS+d][c]
__device__ __nv_bfloat16 g_wo_hi[(size_t)CC*CC], g_wo_lo[(size_t)CC*CC];           // [n][k]
__device__ __nv_bfloat16 g_qhi[(size_t)BB*HH*TT*HS], g_qlo[(size_t)BB*HH*TT*HS];   // [B,H,T,HS]
__device__ __nv_bfloat16 g_khi[(size_t)BB*HH*TT*HS], g_klo[(size_t)BB*HH*TT*HS];   // [B,H,T,HS]
__device__ __nv_bfloat16 g_vthi[(size_t)BB*HH*HS*TT], g_vtlo[(size_t)BB*HH*HS*TT]; // [B,H,HS,T] (V^T)
__device__ __nv_bfloat16 g_yhi[(size_t)MM*CC],  g_ylo[(size_t)MM*CC];              // [B,T,C]

// ---------------------------------------------------------------------------
// PTX helpers (compute_103-safe: sm_80+ mma.sync / ldmatrix / cp.async)
// ---------------------------------------------------------------------------
__device__ __forceinline__ uint32_t smem_u32(const void* p) {
    uint32_t a;
    asm("{ .reg .u64 t; cvta.to.shared.u64 t, %1; cvt.u32.u64 %0, t; }"
        : "=r"(a) : "l"(p));
    return a;
}

#define LDSM4(r, addr) \
    asm volatile("ldmatrix.sync.aligned.m8n8.x4.shared.b16 {%0,%1,%2,%3}, [%4];" \
        : "=r"((r)[0]), "=r"((r)[1]), "=r"((r)[2]), "=r"((r)[3]) : "r"(addr))

#define MMA_BF16(c, a, b) \
    asm volatile("mma.sync.aligned.m16n8k16.row.col.f32.bf16.bf16.f32 " \
        "{%0,%1,%2,%3}, {%4,%5,%6,%7}, {%8,%9}, {%0,%1,%2,%3};" \
        : "+f"((c)[0]), "+f"((c)[1]), "+f"((c)[2]), "+f"((c)[3]) \
        : "r"((a)[0]), "r"((a)[1]), "r"((a)[2]), "r"((a)[3]), \
          "r"((b)[0]), "r"((b)[1]))

#define CP_ASYNC16(saddr, gptr) \
    asm volatile("cp.async.cg.shared.global [%0], [%1], 16;" \
        :: "r"(saddr), "l"(gptr) : "memory")
#define CP_COMMIT() asm volatile("cp.async.commit_group;" ::: "memory")
#define CP_WAIT1()  asm volatile("cp.async.wait_group 1;" ::: "memory")
#define CP_WAIT0()  asm volatile("cp.async.wait_group 0;" ::: "memory")

__device__ __forceinline__ void split1(float v, __nv_bfloat16& h, __nv_bfloat16& l) {
    h = __float2bfloat16(v);
    l = __float2bfloat16(v - __bfloat162float(h));
}
__device__ __forceinline__ uint32_t packb(__nv_bfloat16 a, __nv_bfloat16 b) {
    return (uint32_t)__bfloat16_as_ushort(a) | ((uint32_t)__bfloat16_as_ushort(b) << 16);
}
__device__ __forceinline__ void split2(float v0, float v1, uint32_t& hi, uint32_t& lo) {
    __nv_bfloat16 h0, l0, h1, l1;
    split1(v0, h0, l0); split1(v1, h1, l1);
    hi = packb(h0, h1); lo = packb(l0, l1);
}

// ---------------------------------------------------------------------------
// Prep kernels: fp32 -> (hi, lo) bf16
// ---------------------------------------------------------------------------
__global__ __launch_bounds__(256) void cvt_split(const float* __restrict__ s,
                                                 __nv_bfloat16* __restrict__ hi,
                                                 __nv_bfloat16* __restrict__ lo)
{
    size_t i4 = (size_t)blockIdx.x * 256 + threadIdx.x;
    float4 v = reinterpret_cast<const float4*>(s)[i4];
    __nv_bfloat16 h[4], l[4];
    split1(v.x, h[0], l[0]); split1(v.y, h[1], l[1]);
    split1(v.z, h[2], l[2]); split1(v.w, h[3], l[3]);
    reinterpret_cast<uint2*>(hi)[i4] = make_uint2(packb(h[0], h[1]), packb(h[2], h[3]));
    reinterpret_cast<uint2*>(lo)[i4] = make_uint2(packb(l[0], l[1]), packb(l[2], l[3]));
}

__global__ void cvt_w_t(const float* __restrict__ Wq,
                        const float* __restrict__ Wk,
                        const float* __restrict__ Wv)
{
    __shared__ float ts[32][33];
    const int which = blockIdx.z / HH;
    const int h     = blockIdx.z % HH;
    const float* W  = (which == 0) ? Wq : (which == 1) ? Wk : Wv;
    const int c0 = blockIdx.x * 32;
    const int d0 = blockIdx.y * 32;

    for (int i = threadIdx.y; i < 32; i += 8)
        ts[i][threadIdx.x] = W[((size_t)h * CC + c0 + i) * HS + d0 + threadIdx.x];
    __syncthreads();

    __nv_bfloat16* hi = g_wt_hi + (size_t)which * HH * HS * CC;
    __nv_bfloat16* lo = g_wt_lo + (size_t)which * HH * HS * CC;
    for (int i = threadIdx.y; i < 32; i += 8) {
        int d = d0 + i, c = c0 + threadIdx.x;
        float v = ts[threadIdx.x][i];
        __nv_bfloat16 vh, vl;
        split1(v, vh, vl);
        size_t o = (size_t)(h * HS + d) * CC + c;
        hi[o] = vh;
        lo[o] = vl;
    }
}

// ---------------------------------------------------------------------------
// Split-bf16 HMMA GEMM, 2-stage cp.async pipeline, 2 CTAs/SM.
// Block tile 128(m) x 64(n) x 64(k). Warp tile 32x32 (8 warps: 4m x 2n).
// Stage (48KB): AHI 0, ALO 16K, BHI 32K, BLO 40K. 2 stages = 96KB smem.
// ---------------------------------------------------------------------------
#define GSTG 49152u

__device__ __forceinline__ void gemm_stage_load(
    uint32_t sb, int stage, int tid, int m0,
    const __nv_bfloat16* __restrict__ Ahi, const __nv_bfloat16* __restrict__ Alo,
    const __nv_bfloat16* __restrict__ Bhi, const __nv_bfloat16* __restrict__ Blo,
    int c0)
{
    const uint32_t base = sb + (uint32_t)stage * GSTG;
#pragma unroll
    for (int it = 0; it < 4; it++) {                 // A: 1024 uint4 per buffer
        int idx = tid + it * 256;
        int m = idx >> 3, kv = idx & 7;
        uint32_t soff = (uint32_t)(m * 128 + ((kv ^ (m & 7)) << 4));
        size_t ga = (size_t)(m0 + m) * CC + c0 + kv * 8;
        CP_ASYNC16(base + soff,          Ahi + ga);
        CP_ASYNC16(base + 16384 + soff,  Alo + ga);
    }
#pragma unroll
    for (int it = 0; it < 2; it++) {                 // B: 512 uint4 per buffer
        int idx = tid + it * 256;
        int n = idx >> 3, kv = idx & 7;
        uint32_t soff = (uint32_t)(n * 128 + ((kv ^ (n & 7)) << 4));
        size_t gb = (size_t)n * CC + c0 + kv * 8;
        CP_ASYNC16(base + 32768 + soff,  Bhi + gb);
        CP_ASYNC16(base + 40960 + soff,  Blo + gb);
    }
}

__global__ __launch_bounds__(256, 2) void hmma_gemm(const float* __restrict__ bias,
                                                    float* __restrict__ out_direct,
                                                    int mode)
{
    extern __shared__ unsigned char smem[];
    const uint32_t sb = smem_u32(smem);
    const int tid = threadIdx.x;
    const int wid = tid >> 5, lid = tid & 31;
    const int m0  = blockIdx.x * 128;
    const int warp_m = (wid & 3) * 32;               // 4 warps in m
    const int warp_n = (wid >> 2) * 32;              // 2 warps in n
    const int nbase  = blockIdx.y * 64;
    const int z = blockIdx.z;

    const __nv_bfloat16 *Ahi, *Alo, *Bhi, *Blo;
    if (mode == 0) {
        Ahi = g_xhi; Alo = g_xlo;
        const size_t wo = (size_t)z * HH * HS * CC + (size_t)nbase * CC;
        Bhi = g_wt_hi + wo; Blo = g_wt_lo + wo;
    } else {
        Ahi = g_yhi; Alo = g_ylo;
        Bhi = g_wo_hi + (size_t)nbase * CC;
        Blo = g_wo_lo + (size_t)nbase * CC;
    }

    float acc[2][4][4];
#pragma unroll
    for (int i = 0; i < 2; i++)
#pragma unroll
        for (int j = 0; j < 4; j++)
#pragma unroll
            for (int r = 0; r < 4; r++) acc[i][j][r] = 0.f;

    gemm_stage_load(sb, 0, tid, m0, Ahi, Alo, Bhi, Blo, 0);
    CP_COMMIT();

    for (int c0 = 0; c0 < CC; c0 += 64) {
        const int cur = (c0 >> 6) & 1;
        if (c0 + 64 < CC) {
            gemm_stage_load(sb, cur ^ 1, tid, m0, Ahi, Alo, Bhi, Blo, c0 + 64);
            CP_COMMIT();
            CP_WAIT1();
        } else {
            CP_WAIT0();
        }
        __syncthreads();

        const uint32_t stb = sb + (uint32_t)cur * GSTG;
#pragma unroll
        for (int ks = 0; ks < 4; ks++) {
            const int kb = ks * 2 + (lid >> 4);
            uint32_t aHi[2][4], aLo[2][4], bHi[4][2], bLo[4][2];
#pragma unroll
            for (int i = 0; i < 2; i++) {
                int row = warp_m + i * 16 + (lid & 15);
                uint32_t ad = stb + (uint32_t)(row * 128 + ((kb ^ (row & 7)) << 4));
                LDSM4(aHi[i], ad);
                LDSM4(aLo[i], ad + 16384);
            }
#pragma unroll
            for (int nb = 0; nb < 2; nb++) {
                int row = warp_n + nb * 16 + (lid & 15);
                uint32_t ad = stb + 32768 + (uint32_t)(row * 128 + ((kb ^ (row & 7)) << 4));
                uint32_t q[4];
                LDSM4(q, ad);
                bHi[nb*2][0] = q[0]; bHi[nb*2][1] = q[2];
                bHi[nb*2+1][0] = q[1]; bHi[nb*2+1][1] = q[3];
                LDSM4(q, ad + 8192);
                bLo[nb*2][0] = q[0]; bLo[nb*2][1] = q[2];
                bLo[nb*2+1][0] = q[1]; bLo[nb*2+1][1] = q[3];
            }
#pragma unroll
            for (int i = 0; i < 2; i++)
#pragma unroll
                for (int j = 0; j < 4; j++) {
                    MMA_BF16(acc[i][j], aHi[i], bHi[j]);
                    MMA_BF16(acc[i][j], aLo[i], bHi[j]);
                    MMA_BF16(acc[i][j], aHi[i], bLo[j]);
                }
        }
        __syncthreads();
    }

    const int g = lid >> 2, t4 = lid & 3;

    if (mode == 1) {
#pragma unroll
        for (int i = 0; i < 2; i++)
#pragma unroll
            for (int j = 0; j < 4; j++) {
                const int n = nbase + warp_n + j * 8 + t4 * 2;
                const int r0 = m0 + warp_m + i * 16 + g;
                const float b0 = bias[n], b1 = bias[n + 1];
                *reinterpret_cast<float2*>(out_direct + (size_t)r0 * CC + n) =
                    make_float2(acc[i][j][0] + b0, acc[i][j][1] + b1);
                *reinterpret_cast<float2*>(out_direct + (size_t)(r0 + 8) * CC + n) =
                    make_float2(acc[i][j][2] + b0, acc[i][j][3] + b1);
            }
        return;
    }

    const int head = blockIdx.y;   // BN == HS == 64

    if (z != 2) {
        uint32_t* ohi = reinterpret_cast<uint32_t*>(z == 0 ? g_qhi : g_khi);
        uint32_t* olo = reinterpret_cast<uint32_t*>(z == 0 ? g_qlo : g_klo);
#pragma unroll
        for (int i = 0; i < 2; i++)
#pragma unroll
            for (int j = 0; j < 4; j++) {
                const int d = warp_n + j * 8 + t4 * 2;
                const int r0 = m0 + warp_m + i * 16 + g;
                uint32_t hi, lo;
                {
                    int b = r0 >> 11, tt = r0 & (TT - 1);
                    size_t o = ((((size_t)b * HH + head) * TT + tt) * HS + d) >> 1;
                    split2(acc[i][j][0], acc[i][j][1], hi, lo);
                    ohi[o] = hi; olo[o] = lo;
                }
                {
                    int r1 = r0 + 8;
                    int b = r1 >> 11, tt = r1 & (TT - 1);
                    size_t o = ((((size_t)b * HH + head) * TT + tt) * HS + d) >> 1;
                    split2(acc[i][j][2], acc[i][j][3], hi, lo);
                    ohi[o] = hi; olo[o] = lo;
                }
            }
    } else {
        // v: stage fp32 tile (128 x 64) in smem, write transposed [B,H,HS,T]
        __syncthreads();
        float* ps = reinterpret_cast<float*>(smem);   // [128][64], col ^= (row&31)
#pragma unroll
        for (int i = 0; i < 2; i++)
#pragma unroll
            for (int j = 0; j < 4; j++) {
                int m = warp_m + i * 16 + g;
                int n = warp_n + j * 8 + t4 * 2;
                ps[m * 64 + (n ^ (m & 31))]            = acc[i][j][0];
                ps[m * 64 + ((n + 1) ^ (m & 31))]      = acc[i][j][1];
                int m8 = m + 8;
                ps[m8 * 64 + (n ^ (m8 & 31))]          = acc[i][j][2];
                ps[m8 * 64 + ((n + 1) ^ (m8 & 31))]    = acc[i][j][3];
            }
        __syncthreads();
        uint32_t* ohi = reinterpret_cast<uint32_t*>(g_vthi);
        uint32_t* olo = reinterpret_cast<uint32_t*>(g_vtlo);
#pragma unroll
        for (int it = 0; it < 16; it++) {             // 4096 (d, t-pair) pairs
            int u = tid + it * 256;
            int dl = u >> 6;                          // 0..63 (d)
            int tp = (u & 63) * 2;                    // local m (even)
            float v0 = ps[tp * 64 + (dl ^ (tp & 31))];
            float v1 = ps[(tp + 1) * 64 + (dl ^ ((tp + 1) & 31))];
            uint32_t hi, lo;
            split2(v0, v1, hi, lo);
            int tg = m0 + tp, b = tg >> 11, tt = tg & (TT - 1);
            size_t o = ((((size_t)b * HH + head) * HS + dl) * TT + tt) >> 1;
            ohi[o] = hi; olo[o] = lo;
        }
    }
}

// ---------------------------------------------------------------------------
// Flash attention via split-bf16 HMMA, 2-stage cp.async K/V pipeline.
// __launch_bounds__(256, 2): 96KB smem x2 = 192KB <= 228KB, regs capped
// at 128 to allow 2 CTAs/SM (16 warps) so a second CTA covers sync bubbles.
// SMEM: Q hi/lo resident [0,32K); K/V stages at 32K + s*32K
//   (per stage: KHI 0, KLO 8K, VHI 16K, VLO 24K). Total 96 KB.
// ---------------------------------------------------------------------------
__device__ __forceinline__ void attn_stage_load(
    uint32_t sb, int stage, int tid,
    const __nv_bfloat16* __restrict__ Khi, const __nv_bfloat16* __restrict__ Klo,
    const __nv_bfloat16* __restrict__ Vhi, const __nv_bfloat16* __restrict__ Vlo,
    int k0)
{
    const uint32_t base = sb + 32768u + (uint32_t)stage * 32768u;
#pragma unroll
    for (int it = 0; it < 2; it++) {
        int idx = tid + it * 256;
        int m = idx >> 3, kv = idx & 7;
        uint32_t soff = (uint32_t)(m * 128 + ((kv ^ (m & 7)) << 4));
        size_t ga = (size_t)(k0 + m) * HS + kv * 8;
        size_t gv = (size_t)m * TT + k0 + kv * 8;
        CP_ASYNC16(base + soff,          Khi + ga);
        CP_ASYNC16(base + 8192  + soff,  Klo + ga);
        CP_ASYNC16(base + 16384 + soff,  Vhi + gv);
        CP_ASYNC16(base + 24576 + soff,  Vlo + gv);
    }
}

__global__ __launch_bounds__(256, 2) void attn_mma()
{
    extern __shared__ unsigned char smem[];
    const uint32_t sb = smem_u32(smem);
    const int tid = threadIdx.x, wid = tid >> 5, lid = tid & 31;
    const int gid = lid >> 2, t4 = lid & 3;
    const int qt = gridDim.x - 1 - blockIdx.x;    // long blocks first
    const int bh = blockIdx.y;
    const int q0 = qt * 128;

    const __nv_bfloat16* Qhi = g_qhi + (size_t)bh * TT * HS;
    const __nv_bfloat16* Qlo = g_qlo + (size_t)bh * TT * HS;
    const __nv_bfloat16* Khi = g_khi + (size_t)bh * TT * HS;
    const __nv_bfloat16* Klo = g_klo + (size_t)bh * TT * HS;
    const __nv_bfloat16* Vhi = g_vthi + (size_t)bh * HS * TT;
    const __nv_bfloat16* Vlo = g_vtlo + (size_t)bh * HS * TT;

    // Prologue: Q tile + K/V stage 0 via cp.async (one group)
#pragma unroll
    for (int it = 0; it < 4; it++) {
        int idx = tid + it * 256;
        int m = idx >> 3, kv = idx & 7;
        uint32_t soff = (uint32_t)(m * 128 + ((kv ^ (m & 7)) << 4));
        size_t ga = (size_t)(q0 + m) * HS + kv * 8;
        CP_ASYNC16(sb + soff,          Qhi + ga);
        CP_ASYNC16(sb + 16384 + soff,  Qlo + ga);
    }
    attn_stage_load(sb, 0, tid, Khi, Klo, Vhi, Vlo, 0);
    CP_COMMIT();

    float O[8][4];
#pragma unroll
    for (int j = 0; j < 8; j++)
#pragma unroll
        for (int r = 0; r < 4; r++) O[j][r] = 0.f;
    float m0r = -1e30f, m1r = -1e30f, l0r = 0.f, l1r = 0.f;

    const int r0g = q0 + wid * 16 + gid;
    const int jmax = 2 * qt + 1;

    for (int jt = 0; jt <= jmax; jt++) {
        const int k0 = jt * 64;
        if (jt < jmax) {
            attn_stage_load(sb, (jt + 1) & 1, tid, Khi, Klo, Vhi, Vlo, k0 + 64);
            CP_COMMIT();
            CP_WAIT1();
        } else {
            CP_WAIT0();
        }
        __syncthreads();

        const uint32_t kvb = sb + 32768u + (uint32_t)(jt & 1) * 32768u;

        // ---- S = Q * K^T (16 x 64 per warp)
        float sa[8][4];
#pragma unroll
        for (int j = 0; j < 8; j++)
#pragma unroll
            for (int r = 0; r < 4; r++) sa[j][r] = 0.f;

#pragma unroll
        for (int ks = 0; ks < 4; ks++) {
            const int kb = ks * 2 + (lid >> 4);
            uint32_t aH[4], aL[4];
            {
                int row = wid * 16 + (lid & 15);
                uint32_t ad = sb + (uint32_t)(row * 128 + ((kb ^ (row & 7)) << 4));
                LDSM4(aH, ad);
                LDSM4(aL, ad + 16384);
            }
            uint32_t bH[8][2], bL[8][2];
#pragma unroll
            for (int nb = 0; nb < 4; nb++) {
                int row = nb * 16 + (lid & 15);
                uint32_t ad = kvb + (uint32_t)(row * 128 + ((kb ^ (row & 7)) << 4));
                uint32_t q[4];
                LDSM4(q, ad);
                bH[nb*2][0] = q[0]; bH[nb*2][1] = q[2];
                bH[nb*2+1][0] = q[1]; bH[nb*2+1][1] = q[3];
                LDSM4(q, ad + 8192);
                bL[nb*2][0] = q[0]; bL[nb*2][1] = q[2];
                bL[nb*2+1][0] = q[1]; bL[nb*2+1][1] = q[3];
            }
#pragma unroll
            for (int j = 0; j < 8; j++) {
                MMA_BF16(sa[j], aH, bH[j]);
                MMA_BF16(sa[j], aL, bH[j]);
                MMA_BF16(sa[j], aH, bL[j]);
            }
        }

        // ---- scale + causal mask
#pragma unroll
        for (int j = 0; j < 8; j++)
#pragma unroll
            for (int r = 0; r < 4; r++) sa[j][r] *= 0.125f;

        if (k0 + 63 > q0 + wid * 16) {
#pragma unroll
            for (int j = 0; j < 8; j++) {
                int c = k0 + j * 8 + t4 * 2;
                if (c > r0g)         sa[j][0] = -1e30f;
                if (c + 1 > r0g)     sa[j][1] = -1e30f;
                if (c > r0g + 8)     sa[j][2] = -1e30f;
                if (c + 1 > r0g + 8) sa[j][3] = -1e30f;
            }
        }

        // ---- online softmax
        float mx0 = -1e30f, mx1 = -1e30f;
#pragma unroll
        for (int j = 0; j < 8; j++) {
            mx0 = fmaxf(mx0, fmaxf(sa[j][0], sa[j][1]));
            mx1 = fmaxf(mx1, fmaxf(sa[j][2], sa[j][3]));
        }
        mx0 = fmaxf(mx0, __shfl_xor_sync(0xffffffffu, mx0, 1));
        mx0 = fmaxf(mx0, __shfl_xor_sync(0xffffffffu, mx0, 2));
        mx1 = fmaxf(mx1, __shfl_xor_sync(0xffffffffu, mx1, 1));
        mx1 = fmaxf(mx1, __shfl_xor_sync(0xffffffffu, mx1, 2));

        float mn0 = fmaxf(m0r, mx0), mn1 = fmaxf(m1r, mx1);
        float al0 = __expf(m0r - mn0), al1 = __expf(m1r - mn1);
        m0r = mn0; m1r = mn1;

        float ls0 = 0.f, ls1 = 0.f;
#pragma unroll
        for (int j = 0; j < 8; j++) {
            sa[j][0] = __expf(sa[j][0] - mn0);
            sa[j][1] = __expf(sa[j][1] - mn0);
            sa[j][2] = __expf(sa[j][2] - mn1);
            sa[j][3] = __expf(sa[j][3] - mn1);
            ls0 += sa[j][0] + sa[j][1];
            ls1 += sa[j][2] + sa[j][3];
        }
        ls0 += __shfl_xor_sync(0xffffffffu, ls0, 1);
        ls0 += __shfl_xor_sync(0xffffffffu, ls0, 2);
        ls1 += __shfl_xor_sync(0xffffffffu, ls1, 1);
        ls1 += __shfl_xor_sync(0xffffffffu, ls1, 2);
        l0r = l0r * al0 + ls0;
        l1r = l1r * al1 + ls1;

#pragma unroll
        for (int j = 0; j < 8; j++) {
            O[j][0] *= al0; O[j][1] *= al0;
            O[j][2] *= al1; O[j][3] *= al1;
        }

        // ---- O += P * V^T  (P repacked C-frag -> A-frag, hi/lo split)
#pragma unroll
        for (int kc = 0; kc < 4; kc++) {
            uint32_t pH[4], pL[4];
            split2(sa[2*kc][0],   sa[2*kc][1],   pH[0], pL[0]);
            split2(sa[2*kc][2],   sa[2*kc][3],   pH[1], pL[1]);
            split2(sa[2*kc+1][0], sa[2*kc+1][1], pH[2], pL[2]);
            split2(sa[2*kc+1][2], sa[2*kc+1][3], pH[3], pL[3]);

            const int kb = kc * 2 + (lid >> 4);
            uint32_t vH[8][2], vL[8][2];
#pragma unroll
            for (int nb = 0; nb < 4; nb++) {
                int row = nb * 16 + (lid & 15);
                uint32_t ad = kvb + 16384 + (uint32_t)(row * 128 + ((kb ^ (row & 7)) << 4));
                uint32_t q[4];
                LDSM4(q, ad);
                vH[nb*2][0] = q[0]; vH[nb*2][1] = q[2];
                vH[nb*2+1][0] = q[1]; vH[nb*2+1][1] = q[3];
                LDSM4(q, ad + 8192);
                vL[nb*2][0] = q[0]; vL[nb*2][1] = q[2];
                vL[nb*2+1][0] = q[1]; vL[nb*2+1][1] = q[3];
            }
#pragma unroll
            for (int j = 0; j < 8; j++) {
                MMA_BF16(O[j], pH, vH[j]);
                MMA_BF16(O[j], pL, vH[j]);
                MMA_BF16(O[j], pH, vL[j]);
            }
        }
        __syncthreads();   // release this stage before it is overwritten
    }

    // ---- epilogue: y = O / l, bf16 hi/lo, layout [B,T,C]
    const int b = bh >> 4, h = bh & 15;
    const float inv0 = 1.f / l0r, inv1 = 1.f / l1r;
    uint32_t* yhi = reinterpret_cast<uint32_t*>(g_yhi);
    uint32_t* ylo = reinterpret_cast<uint32_t*>(g_ylo);
    const int t0 = r0g, t1 = r0g + 8;
#pragma unroll
    for (int j = 0; j < 8; j++) {
        int d = h * 64 + j * 8 + t4 * 2;
        uint32_t hi, lo;
        split2(O[j][0] * inv0, O[j][1] * inv0, hi, lo);
        size_t o0 = (((size_t)b * TT + t0) * CC + d) >> 1;
        yhi[o0] = hi; ylo[o0] = lo;
        split2(O[j][2] * inv1, O[j][3] * inv1, hi, lo);
        size_t o1 = (((size_t)b * TT + t1) * CC + d) >> 1;
        yhi[o1] = hi; ylo[o1] = lo;
    }
}

// ---------------------------------------------------------------------------
extern "C" void kernel_launch(void* const* d_in, const int* in_sizes, int n_in,
                              void* d_out, int out_size)
{
    const float* x  = (const float*)d_in[0];
    const float* Wq = (const float*)d_in[1];
    const float* Wk = (const float*)d_in[2];
    const float* Wv = (const float*)d_in[3];
    const float* Wo = (const float*)d_in[4];
    const float* bo = (const float*)d_in[5];
    float* out = (float*)d_out;

    __nv_bfloat16 *xhi, *xlo, *wohi, *wolo;
    cudaGetSymbolAddress((void**)&xhi,  g_xhi);
    cudaGetSymbolAddress((void**)&xlo,  g_xlo);
    cudaGetSymbolAddress((void**)&wohi, g_wo_hi);
    cudaGetSymbolAddress((void**)&wolo, g_wo_lo);

    // Prep: split x, W^T (q,k,v), Wo into hi/lo bf16
    cvt_split<<<(MM * CC) / (256 * 4), 256>>>(x, xhi, xlo);
    cvt_w_t<<<dim3(CC / 32, HS / 32, HH * 3), dim3(32, 8)>>>(Wq, Wk, Wv);
    cvt_split<<<(CC * CC) / (256 * 4), 256>>>(Wo, wohi, wolo);

    cudaFuncSetAttribute(hmma_gemm,
                         cudaFuncAttributeMaxDynamicSharedMemorySize, 98304);
    cudaFuncSetAttribute(attn_mma,
                         cudaFuncAttributeMaxDynamicSharedMemorySize, 98304);

    // QKV projections (epilogue emits bf16 hi/lo q, k, and transposed v)
    hmma_gemm<<<dim3(MM / 128, CC / 64, 3), 256, 98304>>>(nullptr, nullptr, 0);

    // Flash attention on tensor cores
    attn_mma<<<dim3(TT / 128, BB * HH), 256, 98304>>>();

    // Output projection
    hmma_gemm<<<dim3(MM / 128, CC / 64, 1), 256, 98304>>>(bo, out, 1);
}

// round 14
// speedup vs baseline: 3.3137x; 1.0072x over previous
#include <cuda_runtime.h>
#include <cuda_bf16.h>
#include <math.h>
#include <cstdint>

// Problem constants
#define BB 4
#define TT 2048
#define CC 1024
#define HH 16
#define HS 64
#define MM (BB*TT)   // 8192

// ---------------------------------------------------------------------------
// Scratch (device globals: no allocations allowed)
// ---------------------------------------------------------------------------
__device__ __nv_bfloat16 g_xhi[(size_t)MM*CC],  g_xlo[(size_t)MM*CC];
__device__ __nv_bfloat16 g_wt_hi[(size_t)3*HH*HS*CC], g_wt_lo[(size_t)3*HH*HS*CC]; // W^T: [which][h*HS+d][c]
__device__ __nv_bfloat16 g_wo_hi[(size_t)CC*CC], g_wo_lo[(size_t)CC*CC];           // [n][k]
__device__ __nv_bfloat16 g_qhi[(size_t)BB*HH*TT*HS], g_qlo[(size_t)BB*HH*TT*HS];   // [B,H,T,HS]
__device__ __nv_bfloat16 g_khi[(size_t)BB*HH*TT*HS], g_klo[(size_t)BB*HH*TT*HS];   // [B,H,T,HS]
__device__ __nv_bfloat16 g_vthi[(size_t)BB*HH*HS*TT], g_vtlo[(size_t)BB*HH*HS*TT]; // [B,H,HS,T] (V^T)
__device__ __nv_bfloat16 g_yhi[(size_t)MM*CC],  g_ylo[(size_t)MM*CC];              // [B,T,C]

// ---------------------------------------------------------------------------
// PTX helpers (compute_103-safe: sm_80+ mma.sync / ldmatrix / cp.async)
// ---------------------------------------------------------------------------
__device__ __forceinline__ uint32_t smem_u32(const void* p) {
    uint32_t a;
    asm("{ .reg .u64 t; cvta.to.shared.u64 t, %1; cvt.u32.u64 %0, t; }"
        : "=r"(a) : "l"(p));
    return a;
}

#define LDSM4(r, addr) \
    asm volatile("ldmatrix.sync.aligned.m8n8.x4.shared.b16 {%0,%1,%2,%3}, [%4];" \
        : "=r"((r)[0]), "=r"((r)[1]), "=r"((r)[2]), "=r"((r)[3]) : "r"(addr))

#define MMA_BF16(c, a, b) \
    asm volatile("mma.sync.aligned.m16n8k16.row.col.f32.bf16.bf16.f32 " \
        "{%0,%1,%2,%3}, {%4,%5,%6,%7}, {%8,%9}, {%0,%1,%2,%3};" \
        : "+f"((c)[0]), "+f"((c)[1]), "+f"((c)[2]), "+f"((c)[3]) \
        : "r"((a)[0]), "r"((a)[1]), "r"((a)[2]), "r"((a)[3]), \
          "r"((b)[0]), "r"((b)[1]))

#define CP_ASYNC16(saddr, gptr) \
    asm volatile("cp.async.cg.shared.global [%0], [%1], 16;" \
        :: "r"(saddr), "l"(gptr) : "memory")
#define CP_COMMIT() asm volatile("cp.async.commit_group;" ::: "memory")
#define CP_WAIT0()  asm volatile("cp.async.wait_group 0;" ::: "memory")

__device__ __forceinline__ void split1(float v, __nv_bfloat16& h, __nv_bfloat16& l) {
    h = __float2bfloat16(v);
    l = __float2bfloat16(v - __bfloat162float(h));
}
__device__ __forceinline__ uint32_t packb(__nv_bfloat16 a, __nv_bfloat16 b) {
    return (uint32_t)__bfloat16_as_ushort(a) | ((uint32_t)__bfloat16_as_ushort(b) << 16);
}
__device__ __forceinline__ void split2(float v0, float v1, uint32_t& hi, uint32_t& lo) {
    __nv_bfloat16 h0, l0, h1, l1;
    split1(v0, h0, l0); split1(v1, h1, l1);
    hi = packb(h0, h1); lo = packb(l0, l1);
}

// ---------------------------------------------------------------------------
// Prep kernels: fp32 -> (hi, lo) bf16
// ---------------------------------------------------------------------------
__global__ __launch_bounds__(256) void cvt_split(const float* __restrict__ s,
                                                 __nv_bfloat16* __restrict__ hi,
                                                 __nv_bfloat16* __restrict__ lo)
{
    size_t i4 = (size_t)blockIdx.x * 256 + threadIdx.x;
    float4 v = reinterpret_cast<const float4*>(s)[i4];
    __nv_bfloat16 h[4], l[4];
    split1(v.x, h[0], l[0]); split1(v.y, h[1], l[1]);
    split1(v.z, h[2], l[2]); split1(v.w, h[3], l[3]);
    reinterpret_cast<uint2*>(hi)[i4] = make_uint2(packb(h[0], h[1]), packb(h[2], h[3]));
    reinterpret_cast<uint2*>(lo)[i4] = make_uint2(packb(l[0], l[1]), packb(l[2], l[3]));
}

__global__ void cvt_w_t(const float* __restrict__ Wq,
                        const float* __restrict__ Wk,
                        const float* __restrict__ Wv)
{
    __shared__ float ts[32][33];
    const int which = blockIdx.z / HH;
    const int h     = blockIdx.z % HH;
    const float* W  = (which == 0) ? Wq : (which == 1) ? Wk : Wv;
    const int c0 = blockIdx.x * 32;
    const int d0 = blockIdx.y * 32;

    for (int i = threadIdx.y; i < 32; i += 8)
        ts[i][threadIdx.x] = W[((size_t)h * CC + c0 + i) * HS + d0 + threadIdx.x];
    __syncthreads();

    __nv_bfloat16* hi = g_wt_hi + (size_t)which * HH * HS * CC;
    __nv_bfloat16* lo = g_wt_lo + (size_t)which * HH * HS * CC;
    for (int i = threadIdx.y; i < 32; i += 8) {
        int d = d0 + i, c = c0 + threadIdx.x;
        float v = ts[threadIdx.x][i];
        __nv_bfloat16 vh, vl;
        split1(v, vh, vl);
        size_t o = (size_t)(h * HS + d) * CC + c;
        hi[o] = vh;
        lo[o] = vl;
    }
}

// ---------------------------------------------------------------------------
// Split-bf16 HMMA GEMM, 2-stage cp.async pipeline, 2 CTAs/SM.
// Block tile 128(m) x 64(n) x 64(k). Warp tile 32x32 (8 warps: 4m x 2n).
// Stage (48KB): AHI 0, ALO 16K, BHI 32K, BLO 40K. 2 stages = 96KB smem.
// SINGLE barrier per k-tile: loads for stage (it+1)&1 (== stage of it-1)
// are issued AFTER the barrier, so no trailing barrier is needed.
// ---------------------------------------------------------------------------
#define GSTG 49152u

__device__ __forceinline__ void gemm_stage_load(
    uint32_t sb, int stage, int tid, int m0,
    const __nv_bfloat16* __restrict__ Ahi, const __nv_bfloat16* __restrict__ Alo,
    const __nv_bfloat16* __restrict__ Bhi, const __nv_bfloat16* __restrict__ Blo,
    int c0)
{
    const uint32_t base = sb + (uint32_t)stage * GSTG;
#pragma unroll
    for (int it = 0; it < 4; it++) {                 // A: 1024 uint4 per buffer
        int idx = tid + it * 256;
        int m = idx >> 3, kv = idx & 7;
        uint32_t soff = (uint32_t)(m * 128 + ((kv ^ (m & 7)) << 4));
        size_t ga = (size_t)(m0 + m) * CC + c0 + kv * 8;
        CP_ASYNC16(base + soff,          Ahi + ga);
        CP_ASYNC16(base + 16384 + soff,  Alo + ga);
    }
#pragma unroll
    for (int it = 0; it < 2; it++) {                 // B: 512 uint4 per buffer
        int idx = tid + it * 256;
        int n = idx >> 3, kv = idx & 7;
        uint32_t soff = (uint32_t)(n * 128 + ((kv ^ (n & 7)) << 4));
        size_t gb = (size_t)n * CC + c0 + kv * 8;
        CP_ASYNC16(base + 32768 + soff,  Bhi + gb);
        CP_ASYNC16(base + 40960 + soff,  Blo + gb);
    }
}

__global__ __launch_bounds__(256, 2) void hmma_gemm(const float* __restrict__ bias,
                                                    float* __restrict__ out_direct,
                                                    int mode)
{
    extern __shared__ unsigned char smem[];
    const uint32_t sb = smem_u32(smem);
    const int tid = threadIdx.x;
    const int wid = tid >> 5, lid = tid & 31;
    const int m0  = blockIdx.x * 128;
    const int warp_m = (wid & 3) * 32;               // 4 warps in m
    const int warp_n = (wid >> 2) * 32;              // 2 warps in n
    const int nbase  = blockIdx.y * 64;
    const int z = blockIdx.z;

    const __nv_bfloat16 *Ahi, *Alo, *Bhi, *Blo;
    if (mode == 0) {
        Ahi = g_xhi; Alo = g_xlo;
        const size_t wo = (size_t)z * HH * HS * CC + (size_t)nbase * CC;
        Bhi = g_wt_hi + wo; Blo = g_wt_lo + wo;
    } else {
        Ahi = g_yhi; Alo = g_ylo;
        Bhi = g_wo_hi + (size_t)nbase * CC;
        Blo = g_wo_lo + (size_t)nbase * CC;
    }

    float acc[2][4][4];
#pragma unroll
    for (int i = 0; i < 2; i++)
#pragma unroll
        for (int j = 0; j < 4; j++)
#pragma unroll
            for (int r = 0; r < 4; r++) acc[i][j][r] = 0.f;

    gemm_stage_load(sb, 0, tid, m0, Ahi, Alo, Bhi, Blo, 0);
    CP_COMMIT();

    for (int it = 0; it < 16; it++) {
        const int cur = it & 1;
        CP_WAIT0();               // stage cur complete
        __syncthreads();          // all warps past stage cur^1 reads
        if (it + 1 < 16) {        // overwrite stage of it-1: safe after barrier
            gemm_stage_load(sb, cur ^ 1, tid, m0, Ahi, Alo, Bhi, Blo, (it + 1) * 64);
            CP_COMMIT();
        }

        const uint32_t stb = sb + (uint32_t)cur * GSTG;
#pragma unroll
        for (int ks = 0; ks < 4; ks++) {
            const int kb = ks * 2 + (lid >> 4);
            uint32_t aHi[2][4], aLo[2][4], bHi[4][2], bLo[4][2];
#pragma unroll
            for (int i = 0; i < 2; i++) {
                int row = warp_m + i * 16 + (lid & 15);
                uint32_t ad = stb + (uint32_t)(row * 128 + ((kb ^ (row & 7)) << 4));
                LDSM4(aHi[i], ad);
                LDSM4(aLo[i], ad + 16384);
            }
#pragma unroll
            for (int nb = 0; nb < 2; nb++) {
                int row = warp_n + nb * 16 + (lid & 15);
                uint32_t ad = stb + 32768 + (uint32_t)(row * 128 + ((kb ^ (row & 7)) << 4));
                uint32_t q[4];
                LDSM4(q, ad);
                bHi[nb*2][0] = q[0]; bHi[nb*2][1] = q[2];
                bHi[nb*2+1][0] = q[1]; bHi[nb*2+1][1] = q[3];
                LDSM4(q, ad + 8192);
                bLo[nb*2][0] = q[0]; bLo[nb*2][1] = q[2];
                bLo[nb*2+1][0] = q[1]; bLo[nb*2+1][1] = q[3];
            }
#pragma unroll
            for (int i = 0; i < 2; i++)
#pragma unroll
                for (int j = 0; j < 4; j++) {
                    MMA_BF16(acc[i][j], aHi[i], bHi[j]);
                    MMA_BF16(acc[i][j], aLo[i], bHi[j]);
                    MMA_BF16(acc[i][j], aHi[i], bLo[j]);
                }
        }
    }

    const int g = lid >> 2, t4 = lid & 3;

    if (mode == 1) {
#pragma unroll
        for (int i = 0; i < 2; i++)
#pragma unroll
            for (int j = 0; j < 4; j++) {
                const int n = nbase + warp_n + j * 8 + t4 * 2;
                const int r0 = m0 + warp_m + i * 16 + g;
                const float b0 = bias[n], b1 = bias[n + 1];
                *reinterpret_cast<float2*>(out_direct + (size_t)r0 * CC + n) =
                    make_float2(acc[i][j][0] + b0, acc[i][j][1] + b1);
                *reinterpret_cast<float2*>(out_direct + (size_t)(r0 + 8) * CC + n) =
                    make_float2(acc[i][j][2] + b0, acc[i][j][3] + b1);
            }
        return;
    }

    const int head = blockIdx.y;   // BN == HS == 64

    if (z != 2) {
        uint32_t* ohi = reinterpret_cast<uint32_t*>(z == 0 ? g_qhi : g_khi);
        uint32_t* olo = reinterpret_cast<uint32_t*>(z == 0 ? g_qlo : g_klo);
#pragma unroll
        for (int i = 0; i < 2; i++)
#pragma unroll
            for (int j = 0; j < 4; j++) {
                const int d = warp_n + j * 8 + t4 * 2;
                const int r0 = m0 + warp_m + i * 16 + g;
                uint32_t hi, lo;
                {
                    int b = r0 >> 11, tt = r0 & (TT - 1);
                    size_t o = ((((size_t)b * HH + head) * TT + tt) * HS + d) >> 1;
                    split2(acc[i][j][0], acc[i][j][1], hi, lo);
                    ohi[o] = hi; olo[o] = lo;
                }
                {
                    int r1 = r0 + 8;
                    int b = r1 >> 11, tt = r1 & (TT - 1);
                    size_t o = ((((size_t)b * HH + head) * TT + tt) * HS + d) >> 1;
                    split2(acc[i][j][2], acc[i][j][3], hi, lo);
                    ohi[o] = hi; olo[o] = lo;
                }
            }
    } else {
        // v: stage fp32 tile (128 x 64) in smem, write transposed [B,H,HS,T]
        __syncthreads();
        float* ps = reinterpret_cast<float*>(smem);   // [128][64], col ^= (row&31)
#pragma unroll
        for (int i = 0; i < 2; i++)
#pragma unroll
            for (int j = 0; j < 4; j++) {
                int m = warp_m + i * 16 + g;
                int n = warp_n + j * 8 + t4 * 2;
                ps[m * 64 + (n ^ (m & 31))]            = acc[i][j][0];
                ps[m * 64 + ((n + 1) ^ (m & 31))]      = acc[i][j][1];
                int m8 = m + 8;
                ps[m8 * 64 + (n ^ (m8 & 31))]          = acc[i][j][2];
                ps[m8 * 64 + ((n + 1) ^ (m8 & 31))]    = acc[i][j][3];
            }
        __syncthreads();
        uint32_t* ohi = reinterpret_cast<uint32_t*>(g_vthi);
        uint32_t* olo = reinterpret_cast<uint32_t*>(g_vtlo);
#pragma unroll
        for (int it = 0; it < 16; it++) {             // 4096 (d, t-pair) pairs
            int u = tid + it * 256;
            int dl = u >> 6;                          // 0..63 (d)
            int tp = (u & 63) * 2;                    // local m (even)
            float v0 = ps[tp * 64 + (dl ^ (tp & 31))];
            float v1 = ps[(tp + 1) * 64 + (dl ^ ((tp + 1) & 31))];
            uint32_t hi, lo;
            split2(v0, v1, hi, lo);
            int tg = m0 + tp, b = tg >> 11, tt = tg & (TT - 1);
            size_t o = ((((size_t)b * HH + head) * HS + dl) * TT + tt) >> 1;
            ohi[o] = hi; olo[o] = lo;
        }
    }
}

// ---------------------------------------------------------------------------
// Flash attention via split-bf16 HMMA, 2-stage cp.async K/V pipeline.
// Single barrier per tile (loads after barrier; no trailing barrier).
// __launch_bounds__(256, 2): 96KB smem x2 = 192KB <= 228KB.
// SMEM: Q hi/lo resident [0,32K); K/V stages at 32K + s*32K
//   (per stage: KHI 0, KLO 8K, VHI 16K, VLO 24K). Total 96 KB.
// ---------------------------------------------------------------------------
__device__ __forceinline__ void attn_stage_load(
    uint32_t sb, int stage, int tid,
    const __nv_bfloat16* __restrict__ Khi, const __nv_bfloat16* __restrict__ Klo,
    const __nv_bfloat16* __restrict__ Vhi, const __nv_bfloat16* __restrict__ Vlo,
    int k0)
{
    const uint32_t base = sb + 32768u + (uint32_t)stage * 32768u;
#pragma unroll
    for (int it = 0; it < 2; it++) {
        int idx = tid + it * 256;
        int m = idx >> 3, kv = idx & 7;
        uint32_t soff = (uint32_t)(m * 128 + ((kv ^ (m & 7)) << 4));
        size_t ga = (size_t)(k0 + m) * HS + kv * 8;
        size_t gv = (size_t)m * TT + k0 + kv * 8;
        CP_ASYNC16(base + soff,          Khi + ga);
        CP_ASYNC16(base + 8192  + soff,  Klo + ga);
        CP_ASYNC16(base + 16384 + soff,  Vhi + gv);
        CP_ASYNC16(base + 24576 + soff,  Vlo + gv);
    }
}

__global__ __launch_bounds__(256, 2) void attn_mma()
{
    extern __shared__ unsigned char smem[];
    const uint32_t sb = smem_u32(smem);
    const int tid = threadIdx.x, wid = tid >> 5, lid = tid & 31;
    const int gid = lid >> 2, t4 = lid & 3;
    const int qt = gridDim.x - 1 - blockIdx.x;    // long blocks first
    const int bh = blockIdx.y;
    const int q0 = qt * 128;

    const __nv_bfloat16* Qhi = g_qhi + (size_t)bh * TT * HS;
    const __nv_bfloat16* Qlo = g_qlo + (size_t)bh * TT * HS;
    const __nv_bfloat16* Khi = g_khi + (size_t)bh * TT * HS;
    const __nv_bfloat16* Klo = g_klo + (size_t)bh * TT * HS;
    const __nv_bfloat16* Vhi = g_vthi + (size_t)bh * HS * TT;
    const __nv_bfloat16* Vlo = g_vtlo + (size_t)bh * HS * TT;

    // Prologue: Q tile + K/V stage 0 via cp.async (one group)
#pragma unroll
    for (int it = 0; it < 4; it++) {
        int idx = tid + it * 256;
        int m = idx >> 3, kv = idx & 7;
        uint32_t soff = (uint32_t)(m * 128 + ((kv ^ (m & 7)) << 4));
        size_t ga = (size_t)(q0 + m) * HS + kv * 8;
        CP_ASYNC16(sb + soff,          Qhi + ga);
        CP_ASYNC16(sb + 16384 + soff,  Qlo + ga);
    }
    attn_stage_load(sb, 0, tid, Khi, Klo, Vhi, Vlo, 0);
    CP_COMMIT();

    float O[8][4];
#pragma unroll
    for (int j = 0; j < 8; j++)
#pragma unroll
        for (int r = 0; r < 4; r++) O[j][r] = 0.f;
    float m0r = -1e30f, m1r = -1e30f, l0r = 0.f, l1r = 0.f;

    const int r0g = q0 + wid * 16 + gid;
    const int jmax = 2 * qt + 1;

    for (int jt = 0; jt <= jmax; jt++) {
        const int k0 = jt * 64;
        CP_WAIT0();               // stage jt&1 complete
        __syncthreads();          // all warps done reading stage (jt-1)&1
        if (jt < jmax) {          // overwrite stage of jt-1: safe after barrier
            attn_stage_load(sb, (jt + 1) & 1, tid, Khi, Klo, Vhi, Vlo, k0 + 64);
            CP_COMMIT();
        }

        const uint32_t kvb = sb + 32768u + (uint32_t)(jt & 1) * 32768u;

        // ---- S = Q * K^T (16 x 64 per warp)
        float sa[8][4];
#pragma unroll
        for (int j = 0; j < 8; j++)
#pragma unroll
            for (int r = 0; r < 4; r++) sa[j][r] = 0.f;

#pragma unroll
        for (int ks = 0; ks < 4; ks++) {
            const int kb = ks * 2 + (lid >> 4);
            uint32_t aH[4], aL[4];
            {
                int row = wid * 16 + (lid & 15);
                uint32_t ad = sb + (uint32_t)(row * 128 + ((kb ^ (row & 7)) << 4));
                LDSM4(aH, ad);
                LDSM4(aL, ad + 16384);
            }
            uint32_t bH[8][2], bL[8][2];
#pragma unroll
            for (int nb = 0; nb < 4; nb++) {
                int row = nb * 16 + (lid & 15);
                uint32_t ad = kvb + (uint32_t)(row * 128 + ((kb ^ (row & 7)) << 4));
                uint32_t q[4];
                LDSM4(q, ad);
                bH[nb*2][0] = q[0]; bH[nb*2][1] = q[2];
                bH[nb*2+1][0] = q[1]; bH[nb*2+1][1] = q[3];
                LDSM4(q, ad + 8192);
                bL[nb*2][0] = q[0]; bL[nb*2][1] = q[2];
                bL[nb*2+1][0] = q[1]; bL[nb*2+1][1] = q[3];
            }
#pragma unroll
            for (int j = 0; j < 8; j++) {
                MMA_BF16(sa[j], aH, bH[j]);
                MMA_BF16(sa[j], aL, bH[j]);
                MMA_BF16(sa[j], aH, bL[j]);
            }
        }

        // ---- scale + causal mask
#pragma unroll
        for (int j = 0; j < 8; j++)
#pragma unroll
            for (int r = 0; r < 4; r++) sa[j][r] *= 0.125f;

        if (k0 + 63 > q0 + wid * 16) {
#pragma unroll
            for (int j = 0; j < 8; j++) {
                int c = k0 + j * 8 + t4 * 2;
                if (c > r0g)         sa[j][0] = -1e30f;
                if (c + 1 > r0g)     sa[j][1] = -1e30f;
                if (c > r0g + 8)     sa[j][2] = -1e30f;
                if (c + 1 > r0g + 8) sa[j][3] = -1e30f;
            }
        }

        // ---- online softmax
        float mx0 = -1e30f, mx1 = -1e30f;
#pragma unroll
        for (int j = 0; j < 8; j++) {
            mx0 = fmaxf(mx0, fmaxf(sa[j][0], sa[j][1]));
            mx1 = fmaxf(mx1, fmaxf(sa[j][2], sa[j][3]));
        }
        mx0 = fmaxf(mx0, __shfl_xor_sync(0xffffffffu, mx0, 1));
        mx0 = fmaxf(mx0, __shfl_xor_sync(0xffffffffu, mx0, 2));
        mx1 = fmaxf(mx1, __shfl_xor_sync(0xffffffffu, mx1, 1));
        mx1 = fmaxf(mx1, __shfl_xor_sync(0xffffffffu, mx1, 2));

        float mn0 = fmaxf(m0r, mx0), mn1 = fmaxf(m1r, mx1);
        float al0 = __expf(m0r - mn0), al1 = __expf(m1r - mn1);
        m0r = mn0; m1r = mn1;

        float ls0 = 0.f, ls1 = 0.f;
#pragma unroll
        for (int j = 0; j < 8; j++) {
            sa[j][0] = __expf(sa[j][0] - mn0);
            sa[j][1] = __expf(sa[j][1] - mn0);
            sa[j][2] = __expf(sa[j][2] - mn1);
            sa[j][3] = __expf(sa[j][3] - mn1);
            ls0 += sa[j][0] + sa[j][1];
            ls1 += sa[j][2] + sa[j][3];
        }
        ls0 += __shfl_xor_sync(0xffffffffu, ls0, 1);
        ls0 += __shfl_xor_sync(0xffffffffu, ls0, 2);
        ls1 += __shfl_xor_sync(0xffffffffu, ls1, 1);
        ls1 += __shfl_xor_sync(0xffffffffu, ls1, 2);
        l0r = l0r * al0 + ls0;
        l1r = l1r * al1 + ls1;

#pragma unroll
        for (int j = 0; j < 8; j++) {
            O[j][0] *= al0; O[j][1] *= al0;
            O[j][2] *= al1; O[j][3] *= al1;
        }

        // ---- O += P * V^T  (P repacked C-frag -> A-frag, hi/lo split)
#pragma unroll
        for (int kc = 0; kc < 4; kc++) {
            uint32_t pH[4], pL[4];
            split2(sa[2*kc][0],   sa[2*kc][1],   pH[0], pL[0]);
            split2(sa[2*kc][2],   sa[2*kc][3],   pH[1], pL[1]);
            split2(sa[2*kc+1][0], sa[2*kc+1][1], pH[2], pL[2]);
            split2(sa[2*kc+1][2], sa[2*kc+1][3], pH[3], pL[3]);

            const int kb = kc * 2 + (lid >> 4);
            uint32_t vH[8][2], vL[8][2];
#pragma unroll
            for (int nb = 0; nb < 4; nb++) {
                int row = nb * 16 + (lid & 15);
                uint32_t ad = kvb + 16384 + (uint32_t)(row * 128 + ((kb ^ (row & 7)) << 4));
                uint32_t q[4];
                LDSM4(q, ad);
                vH[nb*2][0] = q[0]; vH[nb*2][1] = q[2];
                vH[nb*2+1][0] = q[1]; vH[nb*2+1][1] = q[3];
                LDSM4(q, ad + 8192);
                vL[nb*2][0] = q[0]; vL[nb*2][1] = q[2];
                vL[nb*2+1][0] = q[1]; vL[nb*2+1][1] = q[3];
            }
#pragma unroll
            for (int j = 0; j < 8; j++) {
                MMA_BF16(O[j], pH, vH[j]);
                MMA_BF16(O[j], pL, vH[j]);
                MMA_BF16(O[j], pH, vL[j]);
            }
        }
    }

    // ---- epilogue: y = O / l, bf16 hi/lo, layout [B,T,C]
    const int b = bh >> 4, h = bh & 15;
    const float inv0 = 1.f / l0r, inv1 = 1.f / l1r;
    uint32_t* yhi = reinterpret_cast<uint32_t*>(g_yhi);
    uint32_t* ylo = reinterpret_cast<uint32_t*>(g_ylo);
    const int t0 = r0g, t1 = r0g + 8;
#pragma unroll
    for (int j = 0; j < 8; j++) {
        int d = h * 64 + j * 8 + t4 * 2;
        uint32_t hi, lo;
        split2(O[j][0] * inv0, O[j][1] * inv0, hi, lo);
        size_t o0 = (((size_t)b * TT + t0) * CC + d) >> 1;
        yhi[o0] = hi; ylo[o0] = lo;
        split2(O[j][2] * inv1, O[j][3] * inv1, hi, lo);
        size_t o1 = (((size_t)b * TT + t1) * CC + d) >> 1;
        yhi[o1] = hi; ylo[o1] = lo;
    }
}

// ---------------------------------------------------------------------------
extern "C" void kernel_launch(void* const* d_in, const int* in_sizes, int n_in,
                              void* d_out, int out_size)
{
    const float* x  = (const float*)d_in[0];
    const float* Wq = (const float*)d_in[1];
    const float* Wk = (const float*)d_in[2];
    const float* Wv = (const float*)d_in[3];
    const float* Wo = (const float*)d_in[4];
    const float* bo = (const float*)d_in[5];
    float* out = (float*)d_out;

    __nv_bfloat16 *xhi, *xlo, *wohi, *wolo;
    cudaGetSymbolAddress((void**)&xhi,  g_xhi);
    cudaGetSymbolAddress((void**)&xlo,  g_xlo);
    cudaGetSymbolAddress((void**)&wohi, g_wo_hi);
    cudaGetSymbolAddress((void**)&wolo, g_wo_lo);

    // Prep: split x, W^T (q,k,v), Wo into hi/lo bf16
    cvt_split<<<(MM * CC) / (256 * 4), 256>>>(x, xhi, xlo);
    cvt_w_t<<<dim3(CC / 32, HS / 32, HH * 3), dim3(32, 8)>>>(Wq, Wk, Wv);
    cvt_split<<<(CC * CC) / (256 * 4), 256>>>(Wo, wohi, wolo);

    cudaFuncSetAttribute(hmma_gemm,
                         cudaFuncAttributeMaxDynamicSharedMemorySize, 98304);
    cudaFuncSetAttribute(attn_mma,
                         cudaFuncAttributeMaxDynamicSharedMemorySize, 98304);

    // QKV projections (epilogue emits bf16 hi/lo q, k, and transposed v)
    hmma_gemm<<<dim3(MM / 128, CC / 64, 3), 256, 98304>>>(nullptr, nullptr, 0);

    // Flash attention on tensor cores
    attn_mma<<<dim3(TT / 128, BB * HH), 256, 98304>>>();

    // Output projection
    hmma_gemm<<<dim3(MM / 128, CC / 64, 1), 256, 98304>>>(bo, out, 1);
}

// round 16
// speedup vs baseline: 3.3225x; 1.0027x over previous
#include <cuda_runtime.h>
#include <cuda_bf16.h>
#include <math.h>
#include <cstdint>

// Problem constants
#define BB 4
#define TT 2048
#define CC 1024
#define HH 16
#define HS 64
#define MM (BB*TT)   // 8192

// ---------------------------------------------------------------------------
// Scratch (device globals: no allocations allowed)
// ---------------------------------------------------------------------------
__device__ __nv_bfloat16 g_xhi[(size_t)MM*CC],  g_xlo[(size_t)MM*CC];
__device__ __nv_bfloat16 g_wt_hi[(size_t)3*HH*HS*CC], g_wt_lo[(size_t)3*HH*HS*CC]; // W^T: [which][h*HS+d][c]
__device__ __nv_bfloat16 g_wo_hi[(size_t)CC*CC], g_wo_lo[(size_t)CC*CC];           // [n][k]
__device__ __nv_bfloat16 g_qhi[(size_t)BB*HH*TT*HS], g_qlo[(size_t)BB*HH*TT*HS];   // [B,H,T,HS]
__device__ __nv_bfloat16 g_khi[(size_t)BB*HH*TT*HS], g_klo[(size_t)BB*HH*TT*HS];   // [B,H,T,HS]
__device__ __nv_bfloat16 g_vthi[(size_t)BB*HH*HS*TT], g_vtlo[(size_t)BB*HH*HS*TT]; // [B,H,HS,T] (V^T)
__device__ __nv_bfloat16 g_yhi[(size_t)MM*CC],  g_ylo[(size_t)MM*CC];              // [B,T,C]

// ---------------------------------------------------------------------------
// PTX helpers (compute_103-safe: sm_80+ mma.sync / ldmatrix / cp.async)
// ---------------------------------------------------------------------------
__device__ __forceinline__ uint32_t smem_u32(const void* p) {
    uint32_t a;
    asm("{ .reg .u64 t; cvta.to.shared.u64 t, %1; cvt.u32.u64 %0, t; }"
        : "=r"(a) : "l"(p));
    return a;
}

#define LDSM4(r, addr) \
    asm volatile("ldmatrix.sync.aligned.m8n8.x4.shared.b16 {%0,%1,%2,%3}, [%4];" \
        : "=r"((r)[0]), "=r"((r)[1]), "=r"((r)[2]), "=r"((r)[3]) : "r"(addr))

#define MMA_BF16(c, a, b) \
    asm volatile("mma.sync.aligned.m16n8k16.row.col.f32.bf16.bf16.f32 " \
        "{%0,%1,%2,%3}, {%4,%5,%6,%7}, {%8,%9}, {%0,%1,%2,%3};" \
        : "+f"((c)[0]), "+f"((c)[1]), "+f"((c)[2]), "+f"((c)[3]) \
        : "r"((a)[0]), "r"((a)[1]), "r"((a)[2]), "r"((a)[3]), \
          "r"((b)[0]), "r"((b)[1]))

#define CP_ASYNC16(saddr, gptr) \
    asm volatile("cp.async.cg.shared.global [%0], [%1], 16;" \
        :: "r"(saddr), "l"(gptr) : "memory")
#define CP_COMMIT() asm volatile("cp.async.commit_group;" ::: "memory")
#define CP_WAIT0()  asm volatile("cp.async.wait_group 0;" ::: "memory")

__device__ __forceinline__ void split1(float v, __nv_bfloat16& h, __nv_bfloat16& l) {
    h = __float2bfloat16(v);
    l = __float2bfloat16(v - __bfloat162float(h));
}
__device__ __forceinline__ uint32_t packb(__nv_bfloat16 a, __nv_bfloat16 b) {
    return (uint32_t)__bfloat16_as_ushort(a) | ((uint32_t)__bfloat16_as_ushort(b) << 16);
}
__device__ __forceinline__ void split2(float v0, float v1, uint32_t& hi, uint32_t& lo) {
    __nv_bfloat16 h0, l0, h1, l1;
    split1(v0, h0, l0); split1(v1, h1, l1);
    hi = packb(h0, h1); lo = packb(l0, l1);
}

// ---------------------------------------------------------------------------
// Prep kernels: fp32 -> (hi, lo) bf16
// ---------------------------------------------------------------------------
__global__ __launch_bounds__(256) void cvt_split(const float* __restrict__ s,
                                                 __nv_bfloat16* __restrict__ hi,
                                                 __nv_bfloat16* __restrict__ lo)
{
    size_t i4 = (size_t)blockIdx.x * 256 + threadIdx.x;
    float4 v = reinterpret_cast<const float4*>(s)[i4];
    __nv_bfloat16 h[4], l[4];
    split1(v.x, h[0], l[0]); split1(v.y, h[1], l[1]);
    split1(v.z, h[2], l[2]); split1(v.w, h[3], l[3]);
    reinterpret_cast<uint2*>(hi)[i4] = make_uint2(packb(h[0], h[1]), packb(h[2], h[3]));
    reinterpret_cast<uint2*>(lo)[i4] = make_uint2(packb(l[0], l[1]), packb(l[2], l[3]));
}

__global__ void cvt_w_t(const float* __restrict__ Wq,
                        const float* __restrict__ Wk,
                        const float* __restrict__ Wv)
{
    __shared__ float ts[32][33];
    const int which = blockIdx.z / HH;
    const int h     = blockIdx.z % HH;
    const float* W  = (which == 0) ? Wq : (which == 1) ? Wk : Wv;
    const int c0 = blockIdx.x * 32;
    const int d0 = blockIdx.y * 32;

    for (int i = threadIdx.y; i < 32; i += 8)
        ts[i][threadIdx.x] = W[((size_t)h * CC + c0 + i) * HS + d0 + threadIdx.x];
    __syncthreads();

    __nv_bfloat16* hi = g_wt_hi + (size_t)which * HH * HS * CC;
    __nv_bfloat16* lo = g_wt_lo + (size_t)which * HH * HS * CC;
    for (int i = threadIdx.y; i < 32; i += 8) {
        int d = d0 + i, c = c0 + threadIdx.x;
        float v = ts[threadIdx.x][i];
        __nv_bfloat16 vh, vl;
        split1(v, vh, vl);
        size_t o = (size_t)(h * HS + d) * CC + c;
        hi[o] = vh;
        lo[o] = vl;
    }
}

// ---------------------------------------------------------------------------
// Split-bf16 HMMA GEMM (unchanged from R14).
// ---------------------------------------------------------------------------
#define GSTG 49152u

__device__ __forceinline__ void gemm_stage_load(
    uint32_t sb, int stage, int tid, int m0,
    const __nv_bfloat16* __restrict__ Ahi, const __nv_bfloat16* __restrict__ Alo,
    const __nv_bfloat16* __restrict__ Bhi, const __nv_bfloat16* __restrict__ Blo,
    int c0)
{
    const uint32_t base = sb + (uint32_t)stage * GSTG;
#pragma unroll
    for (int it = 0; it < 4; it++) {
        int idx = tid + it * 256;
        int m = idx >> 3, kv = idx & 7;
        uint32_t soff = (uint32_t)(m * 128 + ((kv ^ (m & 7)) << 4));
        size_t ga = (size_t)(m0 + m) * CC + c0 + kv * 8;
        CP_ASYNC16(base + soff,          Ahi + ga);
        CP_ASYNC16(base + 16384 + soff,  Alo + ga);
    }
#pragma unroll
    for (int it = 0; it < 2; it++) {
        int idx = tid + it * 256;
        int n = idx >> 3, kv = idx & 7;
        uint32_t soff = (uint32_t)(n * 128 + ((kv ^ (n & 7)) << 4));
        size_t gb = (size_t)n * CC + c0 + kv * 8;
        CP_ASYNC16(base + 32768 + soff,  Bhi + gb);
        CP_ASYNC16(base + 40960 + soff,  Blo + gb);
    }
}

__global__ __launch_bounds__(256, 2) void hmma_gemm(const float* __restrict__ bias,
                                                    float* __restrict__ out_direct,
                                                    int mode)
{
    extern __shared__ unsigned char smem[];
    const uint32_t sb = smem_u32(smem);
    const int tid = threadIdx.x;
    const int wid = tid >> 5, lid = tid & 31;
    const int m0  = blockIdx.x * 128;
    const int warp_m = (wid & 3) * 32;
    const int warp_n = (wid >> 2) * 32;
    const int nbase  = blockIdx.y * 64;
    const int z = blockIdx.z;

    const __nv_bfloat16 *Ahi, *Alo, *Bhi, *Blo;
    if (mode == 0) {
        Ahi = g_xhi; Alo = g_xlo;
        const size_t wo = (size_t)z * HH * HS * CC + (size_t)nbase * CC;
        Bhi = g_wt_hi + wo; Blo = g_wt_lo + wo;
    } else {
        Ahi = g_yhi; Alo = g_ylo;
        Bhi = g_wo_hi + (size_t)nbase * CC;
        Blo = g_wo_lo + (size_t)nbase * CC;
    }

    float acc[2][4][4];
#pragma unroll
    for (int i = 0; i < 2; i++)
#pragma unroll
        for (int j = 0; j < 4; j++)
#pragma unroll
            for (int r = 0; r < 4; r++) acc[i][j][r] = 0.f;

    gemm_stage_load(sb, 0, tid, m0, Ahi, Alo, Bhi, Blo, 0);
    CP_COMMIT();

    for (int it = 0; it < 16; it++) {
        const int cur = it & 1;
        CP_WAIT0();
        __syncthreads();
        if (it + 1 < 16) {
            gemm_stage_load(sb, cur ^ 1, tid, m0, Ahi, Alo, Bhi, Blo, (it + 1) * 64);
            CP_COMMIT();
        }

        const uint32_t stb = sb + (uint32_t)cur * GSTG;
#pragma unroll
        for (int ks = 0; ks < 4; ks++) {
            const int kb = ks * 2 + (lid >> 4);
            uint32_t aHi[2][4], aLo[2][4], bHi[4][2], bLo[4][2];
#pragma unroll
            for (int i = 0; i < 2; i++) {
                int row = warp_m + i * 16 + (lid & 15);
                uint32_t ad = stb + (uint32_t)(row * 128 + ((kb ^ (row & 7)) << 4));
                LDSM4(aHi[i], ad);
                LDSM4(aLo[i], ad + 16384);
            }
#pragma unroll
            for (int nb = 0; nb < 2; nb++) {
                int row = warp_n + nb * 16 + (lid & 15);
                uint32_t ad = stb + 32768 + (uint32_t)(row * 128 + ((kb ^ (row & 7)) << 4));
                uint32_t q[4];
                LDSM4(q, ad);
                bHi[nb*2][0] = q[0]; bHi[nb*2][1] = q[2];
                bHi[nb*2+1][0] = q[1]; bHi[nb*2+1][1] = q[3];
                LDSM4(q, ad + 8192);
                bLo[nb*2][0] = q[0]; bLo[nb*2][1] = q[2];
                bLo[nb*2+1][0] = q[1]; bLo[nb*2+1][1] = q[3];
            }
#pragma unroll
            for (int i = 0; i < 2; i++)
#pragma unroll
                for (int j = 0; j < 4; j++) {
                    MMA_BF16(acc[i][j], aHi[i], bHi[j]);
                    MMA_BF16(acc[i][j], aLo[i], bHi[j]);
                    MMA_BF16(acc[i][j], aHi[i], bLo[j]);
                }
        }
    }

    const int g = lid >> 2, t4 = lid & 3;

    if (mode == 1) {
#pragma unroll
        for (int i = 0; i < 2; i++)
#pragma unroll
            for (int j = 0; j < 4; j++) {
                const int n = nbase + warp_n + j * 8 + t4 * 2;
                const int r0 = m0 + warp_m + i * 16 + g;
                const float b0 = bias[n], b1 = bias[n + 1];
                *reinterpret_cast<float2*>(out_direct + (size_t)r0 * CC + n) =
                    make_float2(acc[i][j][0] + b0, acc[i][j][1] + b1);
                *reinterpret_cast<float2*>(out_direct + (size_t)(r0 + 8) * CC + n) =
                    make_float2(acc[i][j][2] + b0, acc[i][j][3] + b1);
            }
        return;
    }

    const int head = blockIdx.y;

    if (z != 2) {
        uint32_t* ohi = reinterpret_cast<uint32_t*>(z == 0 ? g_qhi : g_khi);
        uint32_t* olo = reinterpret_cast<uint32_t*>(z == 0 ? g_qlo : g_klo);
#pragma unroll
        for (int i = 0; i < 2; i++)
#pragma unroll
            for (int j = 0; j < 4; j++) {
                const int d = warp_n + j * 8 + t4 * 2;
                const int r0 = m0 + warp_m + i * 16 + g;
                uint32_t hi, lo;
                {
                    int b = r0 >> 11, tt = r0 & (TT - 1);
                    size_t o = ((((size_t)b * HH + head) * TT + tt) * HS + d) >> 1;
                    split2(acc[i][j][0], acc[i][j][1], hi, lo);
                    ohi[o] = hi; olo[o] = lo;
                }
                {
                    int r1 = r0 + 8;
                    int b = r1 >> 11, tt = r1 & (TT - 1);
                    size_t o = ((((size_t)b * HH + head) * TT + tt) * HS + d) >> 1;
                    split2(acc[i][j][2], acc[i][j][3], hi, lo);
                    ohi[o] = hi; olo[o] = lo;
                }
            }
    } else {
        __syncthreads();
        float* ps = reinterpret_cast<float*>(smem);
#pragma unroll
        for (int i = 0; i < 2; i++)
#pragma unroll
            for (int j = 0; j < 4; j++) {
                int m = warp_m + i * 16 + g;
                int n = warp_n + j * 8 + t4 * 2;
                ps[m * 64 + (n ^ (m & 31))]            = acc[i][j][0];
                ps[m * 64 + ((n + 1) ^ (m & 31))]      = acc[i][j][1];
                int m8 = m + 8;
                ps[m8 * 64 + (n ^ (m8 & 31))]          = acc[i][j][2];
                ps[m8 * 64 + ((n + 1) ^ (m8 & 31))]    = acc[i][j][3];
            }
        __syncthreads();
        uint32_t* ohi = reinterpret_cast<uint32_t*>(g_vthi);
        uint32_t* olo = reinterpret_cast<uint32_t*>(g_vtlo);
#pragma unroll
        for (int it = 0; it < 16; it++) {
            int u = tid + it * 256;
            int dl = u >> 6;
            int tp = (u & 63) * 2;
            float v0 = ps[tp * 64 + (dl ^ (tp & 31))];
            float v1 = ps[(tp + 1) * 64 + (dl ^ ((tp + 1) & 31))];
            uint32_t hi, lo;
            split2(v0, v1, hi, lo);
            int tg = m0 + tp, b = tg >> 11, tt = tg & (TT - 1);
            size_t o = ((((size_t)b * HH + head) * HS + dl) * TT + tt) >> 1;
            ohi[o] = hi; olo[o] = lo;
        }
    }
}

// ---------------------------------------------------------------------------
// Flash attention: 4 warps x 32 q-rows (Br=128), 128 threads, 2 CTAs/SM.
// Halves per-SM K/V ldmatrix redundancy vs 8x16 layout at same MMA count.
// SMEM: Q hi/lo [0,32K); K/V stages at 32K + s*32K (KHI/KLO/VHI/VLO 8K each).
// ---------------------------------------------------------------------------
__device__ __forceinline__ void attn_stage_load(
    uint32_t sb, int stage, int tid,
    const __nv_bfloat16* __restrict__ Khi, const __nv_bfloat16* __restrict__ Klo,
    const __nv_bfloat16* __restrict__ Vhi, const __nv_bfloat16* __restrict__ Vlo,
    int k0)
{
    const uint32_t base = sb + 32768u + (uint32_t)stage * 32768u;
#pragma unroll
    for (int it = 0; it < 4; it++) {
        int idx = tid + it * 128;
        int m = idx >> 3, kv = idx & 7;
        uint32_t soff = (uint32_t)(m * 128 + ((kv ^ (m & 7)) << 4));
        size_t ga = (size_t)(k0 + m) * HS + kv * 8;
        size_t gv = (size_t)m * TT + k0 + kv * 8;
        CP_ASYNC16(base + soff,          Khi + ga);
        CP_ASYNC16(base + 8192  + soff,  Klo + ga);
        CP_ASYNC16(base + 16384 + soff,  Vhi + gv);
        CP_ASYNC16(base + 24576 + soff,  Vlo + gv);
    }
}

__global__ __launch_bounds__(128, 2) void attn_mma()
{
    extern __shared__ unsigned char smem[];
    const uint32_t sb = smem_u32(smem);
    const int tid = threadIdx.x, wid = tid >> 5, lid = tid & 31;
    const int gid = lid >> 2, t4 = lid & 3;
    const int qt = gridDim.x - 1 - blockIdx.x;    // long blocks first
    const int bh = blockIdx.y;
    const int q0 = qt * 128;
    const int wm = wid * 32;                      // warp's 32-row slice

    const __nv_bfloat16* Qhi = g_qhi + (size_t)bh * TT * HS;
    const __nv_bfloat16* Qlo = g_qlo + (size_t)bh * TT * HS;
    const __nv_bfloat16* Khi = g_khi + (size_t)bh * TT * HS;
    const __nv_bfloat16* Klo = g_klo + (size_t)bh * TT * HS;
    const __nv_bfloat16* Vhi = g_vthi + (size_t)bh * HS * TT;
    const __nv_bfloat16* Vlo = g_vtlo + (size_t)bh * HS * TT;

    // Prologue: Q tile + K/V stage 0 via cp.async (one group)
#pragma unroll
    for (int it = 0; it < 8; it++) {
        int idx = tid + it * 128;
        int m = idx >> 3, kv = idx & 7;
        uint32_t soff = (uint32_t)(m * 128 + ((kv ^ (m & 7)) << 4));
        size_t ga = (size_t)(q0 + m) * HS + kv * 8;
        CP_ASYNC16(sb + soff,          Qhi + ga);
        CP_ASYNC16(sb + 16384 + soff,  Qlo + ga);
    }
    attn_stage_load(sb, 0, tid, Khi, Klo, Vhi, Vlo, 0);
    CP_COMMIT();

    float O[2][8][4];
#pragma unroll
    for (int i = 0; i < 2; i++)
#pragma unroll
        for (int j = 0; j < 8; j++)
#pragma unroll
            for (int r = 0; r < 4; r++) O[i][j][r] = 0.f;
    float mr[2][2], lr[2][2];
#pragma unroll
    for (int i = 0; i < 2; i++) { mr[i][0] = mr[i][1] = -1e30f; lr[i][0] = lr[i][1] = 0.f; }

    const int jmax = 2 * qt + 1;

    for (int jt = 0; jt <= jmax; jt++) {
        const int k0 = jt * 64;
        CP_WAIT0();
        __syncthreads();
        if (jt < jmax) {
            attn_stage_load(sb, (jt + 1) & 1, tid, Khi, Klo, Vhi, Vlo, k0 + 64);
            CP_COMMIT();
        }

        const uint32_t kvb = sb + 32768u + (uint32_t)(jt & 1) * 32768u;

        // ---- S = Q * K^T (32 x 64 per warp)
        float sa[2][8][4];
#pragma unroll
        for (int i = 0; i < 2; i++)
#pragma unroll
            for (int j = 0; j < 8; j++)
#pragma unroll
                for (int r = 0; r < 4; r++) sa[i][j][r] = 0.f;

#pragma unroll
        for (int ks = 0; ks < 4; ks++) {
            const int kb = ks * 2 + (lid >> 4);
            uint32_t aH[2][4], aL[2][4];
#pragma unroll
            for (int i = 0; i < 2; i++) {
                int row = wm + i * 16 + (lid & 15);
                uint32_t ad = sb + (uint32_t)(row * 128 + ((kb ^ (row & 7)) << 4));
                LDSM4(aH[i], ad);
                LDSM4(aL[i], ad + 16384);
            }
#pragma unroll
            for (int nb = 0; nb < 4; nb++) {
                int row = nb * 16 + (lid & 15);
                uint32_t ad = kvb + (uint32_t)(row * 128 + ((kb ^ (row & 7)) << 4));
                uint32_t q[4], ql[4];
                LDSM4(q, ad);
                LDSM4(ql, ad + 8192);
                uint32_t bH0[2] = {q[0], q[2]},  bH1[2] = {q[1], q[3]};
                uint32_t bL0[2] = {ql[0], ql[2]}, bL1[2] = {ql[1], ql[3]};
#pragma unroll
                for (int i = 0; i < 2; i++) {
                    MMA_BF16(sa[i][nb*2],   aH[i], bH0);
                    MMA_BF16(sa[i][nb*2],   aL[i], bH0);
                    MMA_BF16(sa[i][nb*2],   aH[i], bL0);
                    MMA_BF16(sa[i][nb*2+1], aH[i], bH1);
                    MMA_BF16(sa[i][nb*2+1], aL[i], bH1);
                    MMA_BF16(sa[i][nb*2+1], aH[i], bL1);
                }
            }
        }

        // ---- scale + causal mask
#pragma unroll
        for (int i = 0; i < 2; i++)
#pragma unroll
            for (int j = 0; j < 8; j++)
#pragma unroll
                for (int r = 0; r < 4; r++) sa[i][j][r] *= 0.125f;

#pragma unroll
        for (int i = 0; i < 2; i++) {
            const int rbase = q0 + wm + i * 16;
            if (k0 + 63 > rbase) {
                const int r0 = rbase + gid, r1 = r0 + 8;
#pragma unroll
                for (int j = 0; j < 8; j++) {
                    int c = k0 + j * 8 + t4 * 2;
                    if (c > r0)         sa[i][j][0] = -1e30f;
                    if (c + 1 > r0)     sa[i][j][1] = -1e30f;
                    if (c > r1)         sa[i][j][2] = -1e30f;
                    if (c + 1 > r1)     sa[i][j][3] = -1e30f;
                }
            }
        }

        // ---- online softmax (rows rbase+gid and rbase+gid+8 per i)
#pragma unroll
        for (int i = 0; i < 2; i++) {
            float mx0 = -1e30f, mx1 = -1e30f;
#pragma unroll
            for (int j = 0; j < 8; j++) {
                mx0 = fmaxf(mx0, fmaxf(sa[i][j][0], sa[i][j][1]));
                mx1 = fmaxf(mx1, fmaxf(sa[i][j][2], sa[i][j][3]));
            }
            mx0 = fmaxf(mx0, __shfl_xor_sync(0xffffffffu, mx0, 1));
            mx0 = fmaxf(mx0, __shfl_xor_sync(0xffffffffu, mx0, 2));
            mx1 = fmaxf(mx1, __shfl_xor_sync(0xffffffffu, mx1, 1));
            mx1 = fmaxf(mx1, __shfl_xor_sync(0xffffffffu, mx1, 2));

            float mn0 = fmaxf(mr[i][0], mx0), mn1 = fmaxf(mr[i][1], mx1);
            float al0 = __expf(mr[i][0] - mn0), al1 = __expf(mr[i][1] - mn1);
            mr[i][0] = mn0; mr[i][1] = mn1;

            float ls0 = 0.f, ls1 = 0.f;
#pragma unroll
            for (int j = 0; j < 8; j++) {
                sa[i][j][0] = __expf(sa[i][j][0] - mn0);
                sa[i][j][1] = __expf(sa[i][j][1] - mn0);
                sa[i][j][2] = __expf(sa[i][j][2] - mn1);
                sa[i][j][3] = __expf(sa[i][j][3] - mn1);
                ls0 += sa[i][j][0] + sa[i][j][1];
                ls1 += sa[i][j][2] + sa[i][j][3];
            }
            ls0 += __shfl_xor_sync(0xffffffffu, ls0, 1);
            ls0 += __shfl_xor_sync(0xffffffffu, ls0, 2);
            ls1 += __shfl_xor_sync(0xffffffffu, ls1, 1);
            ls1 += __shfl_xor_sync(0xffffffffu, ls1, 2);
            lr[i][0] = lr[i][0] * al0 + ls0;
            lr[i][1] = lr[i][1] * al1 + ls1;

#pragma unroll
            for (int j = 0; j < 8; j++) {
                O[i][j][0] *= al0; O[i][j][1] *= al0;
                O[i][j][2] *= al1; O[i][j][3] *= al1;
            }
        }

        // ---- O += P * V^T  (P repacked C-frag -> A-frag, hi/lo split)
#pragma unroll
        for (int kc = 0; kc < 4; kc++) {
            uint32_t pH[2][4], pL[2][4];
#pragma unroll
            for (int i = 0; i < 2; i++) {
                split2(sa[i][2*kc][0],   sa[i][2*kc][1],   pH[i][0], pL[i][0]);
                split2(sa[i][2*kc][2],   sa[i][2*kc][3],   pH[i][1], pL[i][1]);
                split2(sa[i][2*kc+1][0], sa[i][2*kc+1][1], pH[i][2], pL[i][2]);
                split2(sa[i][2*kc+1][2], sa[i][2*kc+1][3], pH[i][3], pL[i][3]);
            }

            const int kb = kc * 2 + (lid >> 4);
#pragma unroll
            for (int nb = 0; nb < 4; nb++) {
                int row = nb * 16 + (lid & 15);
                uint32_t ad = kvb + 16384 + (uint32_t)(row * 128 + ((kb ^ (row & 7)) << 4));
                uint32_t q[4], ql[4];
                LDSM4(q, ad);
                LDSM4(ql, ad + 8192);
                uint32_t vH0[2] = {q[0], q[2]},  vH1[2] = {q[1], q[3]};
                uint32_t vL0[2] = {ql[0], ql[2]}, vL1[2] = {ql[1], ql[3]};
#pragma unroll
                for (int i = 0; i < 2; i++) {
                    MMA_BF16(O[i][nb*2],   pH[i], vH0);
                    MMA_BF16(O[i][nb*2],   pL[i], vH0);
                    MMA_BF16(O[i][nb*2],   pH[i], vL0);
                    MMA_BF16(O[i][nb*2+1], pH[i], vH1);
                    MMA_BF16(O[i][nb*2+1], pL[i], vH1);
                    MMA_BF16(O[i][nb*2+1], pH[i], vL1);
                }
            }
        }
    }

    // ---- epilogue: y = O / l, bf16 hi/lo, layout [B,T,C]
    const int b = bh >> 4, h = bh & 15;
    uint32_t* yhi = reinterpret_cast<uint32_t*>(g_yhi);
    uint32_t* ylo = reinterpret_cast<uint32_t*>(g_ylo);
#pragma unroll
    for (int i = 0; i < 2; i++) {
        const float inv0 = 1.f / lr[i][0], inv1 = 1.f / lr[i][1];
        const int t0 = q0 + wm + i * 16 + gid, t1 = t0 + 8;
#pragma unroll
        for (int j = 0; j < 8; j++) {
            int d = h * 64 + j * 8 + t4 * 2;
            uint32_t hi, lo;
            split2(O[i][j][0] * inv0, O[i][j][1] * inv0, hi, lo);
            size_t o0 = (((size_t)b * TT + t0) * CC + d) >> 1;
            yhi[o0] = hi; ylo[o0] = lo;
            split2(O[i][j][2] * inv1, O[i][j][3] * inv1, hi, lo);
            size_t o1 = (((size_t)b * TT + t1) * CC + d) >> 1;
            yhi[o1] = hi; ylo[o1] = lo;
        }
    }
}

// ---------------------------------------------------------------------------
extern "C" void kernel_launch(void* const* d_in, const int* in_sizes, int n_in,
                              void* d_out, int out_size)
{
    const float* x  = (const float*)d_in[0];
    const float* Wq = (const float*)d_in[1];
    const float* Wk = (const float*)d_in[2];
    const float* Wv = (const float*)d_in[3];
    const float* Wo = (const float*)d_in[4];
    const float* bo = (const float*)d_in[5];
    float* out = (float*)d_out;

    __nv_bfloat16 *xhi, *xlo, *wohi, *wolo;
    cudaGetSymbolAddress((void**)&xhi,  g_xhi);
    cudaGetSymbolAddress((void**)&xlo,  g_xlo);
    cudaGetSymbolAddress((void**)&wohi, g_wo_hi);
    cudaGetSymbolAddress((void**)&wolo, g_wo_lo);

    // Prep: split x, W^T (q,k,v), Wo into hi/lo bf16
    cvt_split<<<(MM * CC) / (256 * 4), 256>>>(x, xhi, xlo);
    cvt_w_t<<<dim3(CC / 32, HS / 32, HH * 3), dim3(32, 8)>>>(Wq, Wk, Wv);
    cvt_split<<<(CC * CC) / (256 * 4), 256>>>(Wo, wohi, wolo);

    cudaFuncSetAttribute(hmma_gemm,
                         cudaFuncAttributeMaxDynamicSharedMemorySize, 98304);
    cudaFuncSetAttribute(attn_mma,
                         cudaFuncAttributeMaxDynamicSharedMemorySize, 98304);

    // QKV projections (epilogue emits bf16 hi/lo q, k, and transposed v)
    hmma_gemm<<<dim3(MM / 128, CC / 64, 3), 256, 98304>>>(nullptr, nullptr, 0);

    // Flash attention on tensor cores (4 warps x 32 rows)
    attn_mma<<<dim3(TT / 128, BB * HH), 128, 98304>>>();

    // Output projection
    hmma_gemm<<<dim3(MM / 128, CC / 64, 1), 256, 98304>>>(bo, out, 1);
}